// round 3
// baseline (speedup 1.0000x reference)
#include <cuda_runtime.h>

#define NN 50000
#define NE 600000
#define HH 128
#define NG 128
#define NC 10

// ---------------- scratch (static device globals; no allocation) ------------
__device__ float g_h [NN*HH];      // x @ W per layer
__device__ float g_f0[NN*HH];      // ping
__device__ float g_f1[NN*HH];      // pong
__device__ float g_w [NE];         // CSR edge weights (norm), CSR order
__device__ int   g_src[NE];        // CSR source node ids
__device__ int   g_deg [NN];
__device__ int   g_fill[NN];
__device__ int   g_ptr [NN+1];
__device__ float g_dinv[NN];
__device__ float g_pool[NG*HH];
__device__ float g_cnt [NG];

__device__ __forceinline__ float* selBuf(int s) { return s ? g_f1 : g_f0; }

// ---------------- graph preprocessing --------------------------------------
__global__ void k_zero() {
    int i = blockIdx.x * blockDim.x + threadIdx.x;
    if (i < NN) { g_deg[i] = 0; g_fill[i] = 0; }
    if (i < NG*HH) g_pool[i] = 0.f;
    if (i < NG) g_cnt[i] = 0.f;
}

__global__ void k_deg(const int* __restrict__ ei) {
    int e = blockIdx.x * blockDim.x + threadIdx.x;
    if (e < NE) {
        int d = ei[NE + e];
        if (d >= 0 && d < NN) atomicAdd(&g_deg[d], 1);
    }
}

__global__ void k_dinv() {
    int i = blockIdx.x * blockDim.x + threadIdx.x;
    if (i < NN) {
        int d = g_deg[i];
        g_dinv[i] = (d > 0) ? rsqrtf((float)d) : 0.f;
    }
}

// single-block exclusive scan of g_deg -> g_ptr
__global__ void k_scan() {
    __shared__ int sums[1024];
    const int t = threadIdx.x;
    const int CH = (NN + 1023) / 1024;   // 49
    int beg = t * CH;
    int end = beg + CH; if (end > NN) end = NN;
    if (beg > NN) beg = NN;
    int s = 0;
    for (int i = beg; i < end; i++) s += g_deg[i];
    sums[t] = s;
    __syncthreads();
    for (int off = 1; off < 1024; off <<= 1) {
        int v = (t >= off) ? sums[t - off] : 0;
        __syncthreads();
        sums[t] += v;
        __syncthreads();
    }
    int prefix = (t == 0) ? 0 : sums[t - 1];
    for (int i = beg; i < end; i++) {
        g_ptr[i] = prefix;
        prefix += g_deg[i];
    }
    if (t == 1023) g_ptr[NN] = prefix;
}

__global__ void k_fill(const int* __restrict__ ei) {
    int e = blockIdx.x * blockDim.x + threadIdx.x;
    if (e < NE) {
        int s = ei[e];
        int d = ei[NE + e];
        if (s < 0 || s >= NN || d < 0 || d >= NN) return;
        float w = g_dinv[s] * g_dinv[d];
        int pos = g_ptr[d] + atomicAdd(&g_fill[d], 1);
        g_src[pos] = s;
        g_w[pos] = w;
    }
}

// ---------------- dual GEMM: h = relu?(X)@W ; fout = relu?(X)@R + b ---------
// inSel: -1 -> external X (layer 0), 0/1 -> g_f0/g_f1
// blockIdx.y == 0 -> W into g_h (no bias); == 1 -> R into fout (+bias)
__global__ void __launch_bounds__(256) k_gemm(
    const float* __restrict__ Xext, int inSel, int outSel,
    const float* __restrict__ W, const float* __restrict__ R,
    const float* __restrict__ bias)
{
    __shared__ float As[16][128];
    __shared__ float Bs[16][128];
    const float* X = (inSel < 0) ? Xext : selBuf(inSel);
    const int reluIn = (inSel >= 0);
    const float* Wt = blockIdx.y ? R : W;
    float* out = blockIdx.y ? selBuf(outSel) : g_h;
    const int tid = threadIdx.x;
    const int row0 = blockIdx.x * 128;
    const int tx = tid & 15, ty = tid >> 4;

    float acc[8][8];
#pragma unroll
    for (int i = 0; i < 8; i++)
#pragma unroll
        for (int j = 0; j < 8; j++) acc[i][j] = 0.f;

    for (int k0 = 0; k0 < 128; k0 += 16) {
#pragma unroll
        for (int u = 0; u < 2; u++) {
            int idx = tid + u * 256;     // 0..511
            int r = idx >> 2;            // 0..127
            int c4 = idx & 3;            // float4 within 16-wide k chunk
            int gr = row0 + r;
            float4 v = make_float4(0.f, 0.f, 0.f, 0.f);
            if (gr < NN) v = *(const float4*)(X + gr * 128 + k0 + c4 * 4);
            if (reluIn) {
                v.x = fmaxf(v.x, 0.f); v.y = fmaxf(v.y, 0.f);
                v.z = fmaxf(v.z, 0.f); v.w = fmaxf(v.w, 0.f);
            }
            As[c4 * 4 + 0][r] = v.x;
            As[c4 * 4 + 1][r] = v.y;
            As[c4 * 4 + 2][r] = v.z;
            As[c4 * 4 + 3][r] = v.w;
        }
#pragma unroll
        for (int u = 0; u < 2; u++) {
            int idx = tid + u * 256;
            int r = idx >> 5;            // 0..15
            int c4 = idx & 31;           // 0..31
            *(float4*)&Bs[r][c4 * 4] = *(const float4*)(Wt + (k0 + r) * 128 + c4 * 4);
        }
        __syncthreads();
#pragma unroll
        for (int k = 0; k < 16; k++) {
            float4 a0 = *(float4*)&As[k][ty * 8];
            float4 a1 = *(float4*)&As[k][ty * 8 + 4];
            float4 b0 = *(float4*)&Bs[k][tx * 8];
            float4 b1 = *(float4*)&Bs[k][tx * 8 + 4];
            float av[8] = {a0.x, a0.y, a0.z, a0.w, a1.x, a1.y, a1.z, a1.w};
            float bv[8] = {b0.x, b0.y, b0.z, b0.w, b1.x, b1.y, b1.z, b1.w};
#pragma unroll
            for (int i = 0; i < 8; i++)
#pragma unroll
                for (int j = 0; j < 8; j++)
                    acc[i][j] += av[i] * bv[j];
        }
        __syncthreads();
    }

    const bool addB = (blockIdx.y != 0);
    float bcol[8];
#pragma unroll
    for (int j = 0; j < 8; j++) bcol[j] = addB ? bias[tx * 8 + j] : 0.f;

#pragma unroll
    for (int i = 0; i < 8; i++) {
        int gr = row0 + ty * 8 + i;
        if (gr < NN) {
            float4 o0, o1;
            o0.x = acc[i][0] + bcol[0]; o0.y = acc[i][1] + bcol[1];
            o0.z = acc[i][2] + bcol[2]; o0.w = acc[i][3] + bcol[3];
            o1.x = acc[i][4] + bcol[4]; o1.y = acc[i][5] + bcol[5];
            o1.z = acc[i][6] + bcol[6]; o1.w = acc[i][7] + bcol[7];
            *(float4*)(out + gr * 128 + tx * 8)     = o0;
            *(float4*)(out + gr * 128 + tx * 8 + 4) = o1;
        }
    }
}

// ---------------- CSR aggregation: f[i] += sum_e w[e]*h[src[e]] -------------
__global__ void k_agg(int outSel) {
    const float* __restrict__ h = g_h;
    float* f = selBuf(outSel);
    const int i = blockIdx.x;
    const int t = threadIdx.x;
    const int beg = g_ptr[i], end = g_ptr[i + 1];
    float acc = f[i * HH + t];
    for (int e = beg; e < end; e++) {
        int s = g_src[e];
        float w = g_w[e];
        acc += h[s * HH + t] * w;
    }
    f[i * HH + t] = acc;
}

// ---------------- relu + write `last` + mean-pool accumulation -------------
__global__ void k_pool(int inSel,
                       const int* __restrict__ batch,
                       float* __restrict__ lastOut) {
    const float* f = selBuf(inSel);
    const int t = threadIdx.x;       // feature
    const int base = blockIdx.x * 64;
    float acc = 0.f;
    int cur = -1;
    for (int r = 0; r < 64; r++) {
        int i = base + r;
        if (i >= NN) break;
        float v = fmaxf(f[i * HH + t], 0.f);
        lastOut[i * HH + t] = v;
        int bg = batch[i];
        if (bg != cur) {
            if (cur >= 0) atomicAdd(&g_pool[cur * HH + t], acc);
            cur = bg; acc = 0.f;
        }
        acc += v;
    }
    if (cur >= 0) atomicAdd(&g_pool[cur * HH + t], acc);
    if (t == 0) {
        int c = 0; int cb = -1;
        for (int r = 0; r < 64; r++) {
            int i = base + r;
            if (i >= NN) break;
            int bg = batch[i];
            if (bg != cb) {
                if (cb >= 0) atomicAdd(&g_cnt[cb], (float)c);
                cb = bg; c = 0;
            }
            c++;
        }
        if (cb >= 0) atomicAdd(&g_cnt[cb], (float)c);
    }
}

// ---------------- MLP head + log_softmax ------------------------------------
__global__ void k_head(const float* __restrict__ l1w, const float* __restrict__ l1b,
                       const float* __restrict__ l2w, const float* __restrict__ l2b,
                       float* __restrict__ out) {
    __shared__ float p[HH];
    __shared__ float gg[HH];
    __shared__ float lg[NC];
    const int g = blockIdx.x, t = threadIdx.x;
    float c = fmaxf(g_cnt[g], 1.f);
    p[t] = g_pool[g * HH + t] / c;
    __syncthreads();
    float a = l1b[t];
#pragma unroll 8
    for (int k = 0; k < HH; k++) a += p[k] * l1w[k * HH + t];
    gg[t] = fmaxf(a, 0.f);
    __syncthreads();
    if (t < NC) {
        float a2 = l2b[t];
        for (int k = 0; k < HH; k++) a2 += gg[k] * l2w[k * NC + t];
        lg[t] = a2;
    }
    __syncthreads();
    if (t < NC) {
        float m = lg[0];
        for (int j = 1; j < NC; j++) m = fmaxf(m, lg[j]);
        float s = 0.f;
        for (int j = 0; j < NC; j++) s += expf(lg[j] - m);
        out[g * NC + t] = lg[t] - m - logf(s);
    }
}

// ---------------- launch -----------------------------------------------------
extern "C" void kernel_launch(void* const* d_in, const int* in_sizes, int n_in,
                              void* d_out, int out_size) {
    const float* x     = (const float*)d_in[0];
    const int*   ei    = (const int*)d_in[1];
    const int*   batch = (const int*)d_in[2];
    const float* W1    = (const float*)d_in[3];
    const float* R1    = (const float*)d_in[4];
    const float* b1    = (const float*)d_in[5];
    const float* Wc    = (const float*)d_in[6];
    const float* Rc    = (const float*)d_in[7];
    const float* bc    = (const float*)d_in[8];
    const float* l1w   = (const float*)d_in[9];
    const float* l1b   = (const float*)d_in[10];
    const float* l2w   = (const float*)d_in[11];
    const float* l2b   = (const float*)d_in[12];
    float* out     = (float*)d_out;
    float* lastOut = out + NG * NC;   // tuple order: (log_softmax, last)

    // graph preprocessing (structure + norm is layer-invariant)
    k_zero<<<(NN + 255) / 256, 256>>>();
    k_deg <<<(NE + 255) / 256, 256>>>(ei);
    k_dinv<<<(NN + 255) / 256, 256>>>();
    k_scan<<<1, 1024>>>();
    k_fill<<<(NE + 255) / 256, 256>>>(ei);

    // 4 GCS layers (relu folded into next layer's GEMM load)
    dim3 gg((NN + 127) / 128, 2);
    int inSel = -1;
    int outSel = 0;
    for (int l = 0; l < 4; l++) {
        const float *W, *R, *b;
        if (l == 0) { W = W1; R = R1; b = b1; }
        else { W = Wc + (l - 1) * HH * HH; R = Rc + (l - 1) * HH * HH; b = bc + (l - 1) * HH; }
        k_gemm<<<gg, 256>>>(x, inSel, outSel, W, R, b);
        k_agg<<<NN, 128>>>(outSel);
        inSel = outSel;
        outSel ^= 1;
    }

    // final relu + last output + mean pool (inSel holds last layer's buffer)
    k_pool<<<(NN + 63) / 64, 128>>>(inSel, batch, lastOut);
    k_head<<<NG, 128>>>(l1w, l1b, l2w, l2b, out);
}

// round 5
// speedup vs baseline: 1.9554x; 1.9554x over previous
#include <cuda_runtime.h>
#include <cuda_bf16.h>
#include <cstdint>

#define NN 50000
#define NE 600000
#define HH 128
#define NG 128
#define NC 10
#define NTILES ((NN + 127) / 128)   // 391

// ---------------- scratch (static device globals; no allocation) ------------
__device__ float g_h [NN*HH];
__device__ float g_f0[NN*HH];
__device__ float g_f1[NN*HH];
__device__ float g_w [NE];
__device__ int   g_src[NE];
__device__ int   g_deg [NN];
__device__ int   g_fill[NN];
__device__ int   g_beg [NN];
__device__ int   g_total;
__device__ float g_dinv[NN];
__device__ float g_pool[NG*HH];
__device__ float g_cnt [NG];

__device__ __forceinline__ float* selBuf(int s) { return s ? g_f1 : g_f0; }

__device__ __forceinline__ uint32_t s2u(const void* p) {
    uint32_t a;
    asm("{ .reg .u64 t; cvta.to.shared.u64 t, %1; cvt.u32.u64 %0, t; }"
        : "=r"(a) : "l"(p));
    return a;
}

// ---------------- SMEM layout: bf16 tiles, 272B row stride -------------------
#define TSTRIDE 272                 // 128 bf16 (256B) + 16B pad -> ldmatrix conflict-free
#define TILE_B  (128 * TSTRIDE)     // 34816
#define OFF_AHI 0
#define OFF_ALO (OFF_AHI + TILE_B)
#define OFF_WHI (OFF_ALO + TILE_B)
#define OFF_WLO (OFF_WHI + TILE_B)
#define OFF_RHI (OFF_WLO + TILE_B)
#define OFF_RLO (OFF_RHI + TILE_B)
#define SM_TOTAL (OFF_RLO + TILE_B)   // 208896

__device__ __forceinline__ void ldm4(uint32_t* r, uint32_t addr) {
    asm volatile("ldmatrix.sync.aligned.m8n8.x4.shared.b16 {%0,%1,%2,%3}, [%4];"
                 : "=r"(r[0]), "=r"(r[1]), "=r"(r[2]), "=r"(r[3]) : "r"(addr));
}
__device__ __forceinline__ void mma16816(float* c, const uint32_t* a,
                                         uint32_t b0, uint32_t b1) {
    asm volatile(
        "mma.sync.aligned.m16n8k16.row.col.f32.bf16.bf16.f32 "
        "{%0,%1,%2,%3}, {%4,%5,%6,%7}, {%8,%9}, {%0,%1,%2,%3};"
        : "+f"(c[0]), "+f"(c[1]), "+f"(c[2]), "+f"(c[3])
        : "r"(a[0]), "r"(a[1]), "r"(a[2]), "r"(a[3]), "r"(b0), "r"(b1));
}

__device__ __forceinline__ uint32_t pack2(float a, float b) {
    __nv_bfloat16 x = __float2bfloat16(a);
    __nv_bfloat16 y = __float2bfloat16(b);
    return (uint32_t)*(unsigned short*)&x | ((uint32_t)*(unsigned short*)&y << 16);
}

// ---------------- dual GEMM via mma.sync ------------------------------------
// g_h = relu?(X)@W ; fout = relu?(X)@R + bias
__global__ void __launch_bounds__(256, 1) k_mmagemm(
    const float* __restrict__ Xext, int inSel, int outSel,
    const float* __restrict__ W, const float* __restrict__ R,
    const float* __restrict__ bias)
{
    extern __shared__ char smem[];
    const uint32_t sbase = s2u(smem);
    const int tid = threadIdx.x;
    const int wid = tid >> 5, lane = tid & 31;
    const int row0 = blockIdx.x * 128;
    const float* X = (inSel < 0) ? Xext : selBuf(inSel);
    const bool reluIn = (inSel >= 0);
    float* fout = selBuf(outSel);

    // ---- A tile: fp32 -> bf16 hi/lo, K-contiguous ----
#pragma unroll
    for (int it = 0; it < 16; it++) {
        int idx = it * 256 + tid;          // 4096 float4 slots
        int m = idx >> 5;
        int c4 = (idx & 31) * 4;           // element col
        float4 v = make_float4(0.f, 0.f, 0.f, 0.f);
        int gr = row0 + m;
        if (gr < NN) v = *(const float4*)(X + gr * 128 + c4);
        if (reluIn) {
            v.x = fmaxf(v.x, 0.f); v.y = fmaxf(v.y, 0.f);
            v.z = fmaxf(v.z, 0.f); v.w = fmaxf(v.w, 0.f);
        }
        float hx = __bfloat162float(__float2bfloat16(v.x));
        float hy = __bfloat162float(__float2bfloat16(v.y));
        float hz = __bfloat162float(__float2bfloat16(v.z));
        float hw = __bfloat162float(__float2bfloat16(v.w));
        uint32_t byteOff = m * TSTRIDE + c4 * 2;
        *(uint32_t*)(smem + OFF_AHI + byteOff)     = pack2(v.x, v.y);
        *(uint32_t*)(smem + OFF_AHI + byteOff + 4) = pack2(v.z, v.w);
        *(uint32_t*)(smem + OFF_ALO + byteOff)     = pack2(v.x - hx, v.y - hy);
        *(uint32_t*)(smem + OFF_ALO + byteOff + 4) = pack2(v.z - hz, v.w - hw);
    }
    // ---- W, R tiles: transpose [k][n] -> [n][k], bf16 hi/lo ----
#pragma unroll
    for (int ws = 0; ws < 2; ws++) {
        const float* src = ws ? R : W;
        char* hiB = smem + (ws ? OFF_RHI : OFF_WHI);
        char* loB = smem + (ws ? OFF_RLO : OFF_WLO);
#pragma unroll
        for (int it = 0; it < 16; it++) {
            int idx = it * 256 + tid;
            int k = idx >> 5;
            int n4 = (idx & 31) * 4;
            float4 v = *(const float4*)(src + k * 128 + n4);
            float vv[4] = {v.x, v.y, v.z, v.w};
#pragma unroll
            for (int j = 0; j < 4; j++) {
                __nv_bfloat16 h = __float2bfloat16(vv[j]);
                __nv_bfloat16 l = __float2bfloat16(vv[j] - __bfloat162float(h));
                uint32_t bo = (n4 + j) * TSTRIDE + k * 2;
                *(unsigned short*)(hiB + bo) = *(unsigned short*)&h;
                *(unsigned short*)(loB + bo) = *(unsigned short*)&l;
            }
        }
    }
    __syncthreads();

    // ---- warp tiles: warp_m in {0,1} x 64 rows, warp_n in {0..3} x 64 cols of [W|R]
    const int warp_m = wid & 1;
    const int warp_n = wid >> 1;
    const bool isR = (warp_n >= 2);
    const int colTile = (warp_n & 1) * 64;   // within its matrix

    const uint32_t aHiBase = sbase + OFF_AHI;
    const uint32_t aLoBase = sbase + OFF_ALO;
    const uint32_t bHiBase = sbase + (isR ? OFF_RHI : OFF_WHI);
    const uint32_t bLoBase = sbase + (isR ? OFF_RLO : OFF_WLO);

    // lane address components for ldmatrix
    const uint32_t aOff = (uint32_t)((warp_m * 64 + (lane & 15)) * TSTRIDE
                                     + ((lane >> 4) * 8) * 2);
    const int q = lane >> 3, r8 = lane & 7;
    const uint32_t bOff = (uint32_t)((colTile + ((q & 2) << 2) + r8) * TSTRIDE
                                     + ((q & 1) * 8) * 2);

    float c[4][8][4];
#pragma unroll
    for (int i = 0; i < 4; i++)
#pragma unroll
        for (int j = 0; j < 8; j++)
#pragma unroll
            for (int z = 0; z < 4; z++) c[i][j][z] = 0.f;

#pragma unroll 1
    for (int k0 = 0; k0 < 128; k0 += 16) {
        const uint32_t kB = (uint32_t)(k0 * 2);
#pragma unroll
        for (int term = 0; term < 3; term++) {
            const uint32_t aSel = (term == 2) ? aLoBase : aHiBase;
            const uint32_t bSel = (term == 1) ? bLoBase : bHiBase;
            uint32_t a[4][4];
#pragma unroll
            for (int mf = 0; mf < 4; mf++)
                ldm4(a[mf], aSel + aOff + mf * (16 * TSTRIDE) + kB);
#pragma unroll
            for (int nf2 = 0; nf2 < 4; nf2++) {
                uint32_t bb[4];
                ldm4(bb, bSel + bOff + nf2 * (16 * TSTRIDE) + kB);
#pragma unroll
                for (int mf = 0; mf < 4; mf++) {
                    mma16816(c[mf][nf2 * 2],     a[mf], bb[0], bb[1]);
                    mma16816(c[mf][nf2 * 2 + 1], a[mf], bb[2], bb[3]);
                }
            }
        }
    }

    // ---- epilogue ----
    const int g = lane >> 2, t = lane & 3;
    float* dst = isR ? fout : g_h;
    const int rowBase = row0 + warp_m * 64;
#pragma unroll
    for (int nf = 0; nf < 8; nf++) {
        const int col = colTile + nf * 8 + 2 * t;
        float bx = 0.f, by = 0.f;
        if (isR) {
            float2 bv = *(const float2*)(bias + col);
            bx = bv.x; by = bv.y;
        }
#pragma unroll
        for (int mf = 0; mf < 4; mf++) {
            int rlo = rowBase + mf * 16 + g;
            if (rlo < NN) {
                float2 o = make_float2(c[mf][nf][0] + bx, c[mf][nf][1] + by);
                *(float2*)(dst + rlo * 128 + col) = o;
            }
            if (rlo + 8 < NN) {
                float2 o = make_float2(c[mf][nf][2] + bx, c[mf][nf][3] + by);
                *(float2*)(dst + (rlo + 8) * 128 + col) = o;
            }
        }
    }
}

// ---------------- graph preprocessing --------------------------------------
__global__ void k_zero() {
    int i = blockIdx.x * blockDim.x + threadIdx.x;
    if (i < NN) { g_deg[i] = 0; g_fill[i] = 0; }
    if (i < NG*HH) g_pool[i] = 0.f;
    if (i < NG) g_cnt[i] = 0.f;
    if (i == 0) g_total = 0;
}

__global__ void k_deg(const int* __restrict__ ei) {
    int e = blockIdx.x * blockDim.x + threadIdx.x;
    if (e < NE) {
        int d = ei[NE + e];
        if (d >= 0 && d < NN) atomicAdd(&g_deg[d], 1);
    }
}

__global__ void k_dinv() {
    int i = blockIdx.x * blockDim.x + threadIdx.x;
    if (i < NN) {
        int d = g_deg[i];
        g_dinv[i] = (d > 0) ? rsqrtf((float)d) : 0.f;
    }
}

// per-block scan + one atomic per block (CSR segment order is irrelevant)
__global__ void k_off() {
    __shared__ int sh[256];
    __shared__ int base;
    const int t = threadIdx.x;
    const int i = blockIdx.x * 256 + t;
    int d = (i < NN) ? g_deg[i] : 0;
    sh[t] = d;
    __syncthreads();
    for (int off = 1; off < 256; off <<= 1) {
        int v = (t >= off) ? sh[t - off] : 0;
        __syncthreads();
        sh[t] += v;
        __syncthreads();
    }
    if (t == 255) base = atomicAdd(&g_total, sh[255]);
    __syncthreads();
    if (i < NN) g_beg[i] = base + sh[t] - d;
}

__global__ void k_fill(const int* __restrict__ ei) {
    int e = blockIdx.x * blockDim.x + threadIdx.x;
    if (e < NE) {
        int s = ei[e];
        int d = ei[NE + e];
        if (s < 0 || s >= NN || d < 0 || d >= NN) return;
        float w = g_dinv[s] * g_dinv[d];
        int pos = g_beg[d] + atomicAdd(&g_fill[d], 1);
        g_src[pos] = s;
        g_w[pos] = w;
    }
}

// ---------------- CSR aggregation: warp per node, float4 lanes --------------
__global__ void k_agg(int outSel) {
    float* f = selBuf(outSel);
    const int wid = threadIdx.x >> 5, lane = threadIdx.x & 31;
    const int i = blockIdx.x * 4 + wid;
    if (i >= NN) return;
    const int beg = g_beg[i], d = g_deg[i];
    float4 acc = *(float4*)(f + i * HH + lane * 4);
    for (int e = beg; e < beg + d; e++) {
        int s = g_src[e];
        float w = g_w[e];
        float4 hv = *(const float4*)(g_h + s * HH + lane * 4);
        acc.x += hv.x * w; acc.y += hv.y * w;
        acc.z += hv.z * w; acc.w += hv.w * w;
    }
    *(float4*)(f + i * HH + lane * 4) = acc;
}

// ---------------- relu + write `last` + mean-pool accumulation -------------
__global__ void k_pool(int inSel,
                       const int* __restrict__ batch,
                       float* __restrict__ lastOut) {
    const float* f = selBuf(inSel);
    const int t = threadIdx.x;
    const int base = blockIdx.x * 64;
    float acc = 0.f;
    int cur = -1;
    for (int r = 0; r < 64; r++) {
        int i = base + r;
        if (i >= NN) break;
        float v = fmaxf(f[i * HH + t], 0.f);
        lastOut[i * HH + t] = v;
        int bg = batch[i];
        if (bg != cur) {
            if (cur >= 0) atomicAdd(&g_pool[cur * HH + t], acc);
            cur = bg; acc = 0.f;
        }
        acc += v;
    }
    if (cur >= 0) atomicAdd(&g_pool[cur * HH + t], acc);
    if (t == 0) {
        int c = 0; int cb = -1;
        for (int r = 0; r < 64; r++) {
            int i = base + r;
            if (i >= NN) break;
            int bg = batch[i];
            if (bg != cb) {
                if (cb >= 0) atomicAdd(&g_cnt[cb], (float)c);
                cb = bg; c = 0;
            }
            c++;
        }
        if (cb >= 0) atomicAdd(&g_cnt[cb], (float)c);
    }
}

// ---------------- MLP head + log_softmax ------------------------------------
__global__ void k_head(const float* __restrict__ l1w, const float* __restrict__ l1b,
                       const float* __restrict__ l2w, const float* __restrict__ l2b,
                       float* __restrict__ out) {
    __shared__ float p[HH];
    __shared__ float gg[HH];
    __shared__ float lg[NC];
    const int g = blockIdx.x, t = threadIdx.x;
    float c = fmaxf(g_cnt[g], 1.f);
    p[t] = g_pool[g * HH + t] / c;
    __syncthreads();
    float a = l1b[t];
#pragma unroll 8
    for (int k = 0; k < HH; k++) a += p[k] * l1w[k * HH + t];
    gg[t] = fmaxf(a, 0.f);
    __syncthreads();
    if (t < NC) {
        float a2 = l2b[t];
        for (int k = 0; k < HH; k++) a2 += gg[k] * l2w[k * NC + t];
        lg[t] = a2;
    }
    __syncthreads();
    if (t < NC) {
        float m = lg[0];
        for (int j = 1; j < NC; j++) m = fmaxf(m, lg[j]);
        float s = 0.f;
        for (int j = 0; j < NC; j++) s += expf(lg[j] - m);
        out[g * NC + t] = lg[t] - m - logf(s);
    }
}

// ---------------- launch -----------------------------------------------------
extern "C" void kernel_launch(void* const* d_in, const int* in_sizes, int n_in,
                              void* d_out, int out_size) {
    const float* x     = (const float*)d_in[0];
    const int*   ei    = (const int*)d_in[1];
    const int*   batch = (const int*)d_in[2];
    const float* W1    = (const float*)d_in[3];
    const float* R1    = (const float*)d_in[4];
    const float* b1    = (const float*)d_in[5];
    const float* Wc    = (const float*)d_in[6];
    const float* Rc    = (const float*)d_in[7];
    const float* bc    = (const float*)d_in[8];
    const float* l1w   = (const float*)d_in[9];
    const float* l1b   = (const float*)d_in[10];
    const float* l2w   = (const float*)d_in[11];
    const float* l2b   = (const float*)d_in[12];
    float* out     = (float*)d_out;
    float* lastOut = out + NG * NC;   // tuple order: (log_softmax, last)

    cudaFuncSetAttribute(k_mmagemm, cudaFuncAttributeMaxDynamicSharedMemorySize, SM_TOTAL);

    // graph preprocessing
    k_zero<<<(NN + 255) / 256, 256>>>();
    k_deg <<<(NE + 255) / 256, 256>>>(ei);
    k_dinv<<<(NN + 255) / 256, 256>>>();
    k_off <<<(NN + 255) / 256, 256>>>();
    k_fill<<<(NE + 255) / 256, 256>>>(ei);

    // 4 GCS layers
    int inSel = -1;
    int outSel = 0;
    for (int l = 0; l < 4; l++) {
        const float *W, *R, *b;
        if (l == 0) { W = W1; R = R1; b = b1; }
        else { W = Wc + (l - 1) * HH * HH; R = Rc + (l - 1) * HH * HH; b = bc + (l - 1) * HH; }
        k_mmagemm<<<NTILES, 256, SM_TOTAL>>>(x, inSel, outSel, W, R, b);
        k_agg<<<(NN + 3) / 4, 128>>>(outSel);
        inSel = outSel;
        outSel ^= 1;
    }

    k_pool<<<(NN + 63) / 64, 128>>>(inSel, batch, lastOut);
    k_head<<<NG, 128>>>(l1w, l1b, l2w, l2b, out);
}

// round 6
// speedup vs baseline: 2.9568x; 1.5121x over previous
#include <cuda_runtime.h>
#include <cuda_bf16.h>
#include <cstdint>

#define NN 50000
#define NE 600000
#define HH 128
#define NG 128
#define NC 10
#define NTILES ((NN + 127) / 128)   // 391

// ---------------- SMEM tile geometry ----------------------------------------
#define TSTRIDE 272                 // 128 bf16 (256B) + 16B pad -> ldmatrix conflict-free
#define TILE_B  (128 * TSTRIDE)     // 34816 bytes per 128x128 bf16 tile image

// ---------------- scratch (static device globals; no allocation) ------------
__device__ float g_h [NN*HH];
__device__ float g_f0[NN*HH];
__device__ float g_f1[NN*HH];
__device__ float g_w [NE];
__device__ int   g_src[NE];
__device__ int   g_deg [NN];
__device__ int   g_fill[NN];
__device__ int   g_beg [NN];
__device__ int   g_total;
__device__ float g_dinv[NN];
__device__ float g_pool[NG*HH];
__device__ float g_cnt [NG];
// pre-split weight images: [layer][WHI,WLO,RHI,RLO][TILE_B bytes]
__device__ __align__(16) char g_wimg[4][4][TILE_B];

__device__ __forceinline__ float* selBuf(int s) { return s ? g_f1 : g_f0; }

__device__ __forceinline__ uint32_t s2u(const void* p) {
    uint32_t a;
    asm("{ .reg .u64 t; cvta.to.shared.u64 t, %1; cvt.u32.u64 %0, t; }"
        : "=r"(a) : "l"(p));
    return a;
}

// ---------------- SMEM layout ------------------------------------------------
#define OFF_AHI 0
#define OFF_ALO (OFF_AHI + TILE_B)
#define OFF_WHI (OFF_ALO + TILE_B)
#define OFF_WLO (OFF_WHI + TILE_B)
#define OFF_RHI (OFF_WLO + TILE_B)
#define OFF_RLO (OFF_RHI + TILE_B)
#define SM_TOTAL (OFF_RLO + TILE_B)   // 208896

__device__ __forceinline__ void ldm4(uint32_t* r, uint32_t addr) {
    asm volatile("ldmatrix.sync.aligned.m8n8.x4.shared.b16 {%0,%1,%2,%3}, [%4];"
                 : "=r"(r[0]), "=r"(r[1]), "=r"(r[2]), "=r"(r[3]) : "r"(addr));
}
__device__ __forceinline__ void mma16816(float* c, const uint32_t* a,
                                         uint32_t b0, uint32_t b1) {
    asm volatile(
        "mma.sync.aligned.m16n8k16.row.col.f32.bf16.bf16.f32 "
        "{%0,%1,%2,%3}, {%4,%5,%6,%7}, {%8,%9}, {%0,%1,%2,%3};"
        : "+f"(c[0]), "+f"(c[1]), "+f"(c[2]), "+f"(c[3])
        : "r"(a[0]), "r"(a[1]), "r"(a[2]), "r"(a[3]), "r"(b0), "r"(b1));
}

__device__ __forceinline__ uint32_t pack2(float a, float b) {
    __nv_bfloat16 x = __float2bfloat16(a);
    __nv_bfloat16 y = __float2bfloat16(b);
    return (uint32_t)*(unsigned short*)&x | ((uint32_t)*(unsigned short*)&y << 16);
}

// ---------------- weight pre-split: build SMEM images once per call ---------
// grid: 8 blocks = (layer, W/R), 256 threads
__global__ void k_split(const float* __restrict__ W1, const float* __restrict__ R1,
                        const float* __restrict__ Wc, const float* __restrict__ Rc) {
    const int layer = blockIdx.x >> 1;
    const int isR = blockIdx.x & 1;
    const float* src;
    if (layer == 0) src = isR ? R1 : W1;
    else src = (isR ? Rc : Wc) + (layer - 1) * HH * HH;
    char* hiB = g_wimg[layer][isR * 2];
    char* loB = g_wimg[layer][isR * 2 + 1];
    // idx = n*128 + k; consecutive tid -> consecutive k -> coalesced 2B writes
    for (int idx = threadIdx.x; idx < HH * HH; idx += 256) {
        int n = idx >> 7, k = idx & 127;
        float v = src[k * HH + n];
        __nv_bfloat16 h = __float2bfloat16(v);
        __nv_bfloat16 l = __float2bfloat16(v - __bfloat162float(h));
        uint32_t bo = n * TSTRIDE + k * 2;
        *(unsigned short*)(hiB + bo) = *(unsigned short*)&h;
        *(unsigned short*)(loB + bo) = *(unsigned short*)&l;
    }
}

// ---------------- dual GEMM via mma.sync ------------------------------------
// g_h = relu?(X)@W ; fout = relu?(X)@R + bias
__global__ void __launch_bounds__(256, 1) k_mmagemm(
    const float* __restrict__ Xext, int inSel, int outSel, int layer,
    const float* __restrict__ bias)
{
    extern __shared__ char smem[];
    const uint32_t sbase = s2u(smem);
    const int tid = threadIdx.x;
    const int wid = tid >> 5, lane = tid & 31;
    const int row0 = blockIdx.x * 128;
    const float* X = (inSel < 0) ? Xext : selBuf(inSel);
    const bool reluIn = (inSel >= 0);
    float* fout = selBuf(outSel);

    // ---- A tile: fp32 -> bf16 hi/lo, K-contiguous ----
#pragma unroll
    for (int it = 0; it < 16; it++) {
        int idx = it * 256 + tid;          // 4096 float4 slots
        int m = idx >> 5;
        int c4 = (idx & 31) * 4;
        float4 v = make_float4(0.f, 0.f, 0.f, 0.f);
        int gr = row0 + m;
        if (gr < NN) v = *(const float4*)(X + gr * 128 + c4);
        if (reluIn) {
            v.x = fmaxf(v.x, 0.f); v.y = fmaxf(v.y, 0.f);
            v.z = fmaxf(v.z, 0.f); v.w = fmaxf(v.w, 0.f);
        }
        float hx = __bfloat162float(__float2bfloat16(v.x));
        float hy = __bfloat162float(__float2bfloat16(v.y));
        float hz = __bfloat162float(__float2bfloat16(v.z));
        float hw = __bfloat162float(__float2bfloat16(v.w));
        uint32_t byteOff = m * TSTRIDE + c4 * 2;
        *(uint32_t*)(smem + OFF_AHI + byteOff)     = pack2(v.x, v.y);
        *(uint32_t*)(smem + OFF_AHI + byteOff + 4) = pack2(v.z, v.w);
        *(uint32_t*)(smem + OFF_ALO + byteOff)     = pack2(v.x - hx, v.y - hy);
        *(uint32_t*)(smem + OFF_ALO + byteOff + 4) = pack2(v.z - hz, v.w - hw);
    }
    // ---- W/R images: straight float4 block copy from pre-split global ----
    {
        const float4* src = (const float4*)g_wimg[layer][0];
        float4* dst = (float4*)(smem + OFF_WHI);
        const int n4 = 4 * TILE_B / 16;   // 8704 float4
#pragma unroll
        for (int it = 0; it < 34; it++) {
            int idx = it * 256 + tid;
            if (idx < n4) dst[idx] = src[idx];
        }
    }
    __syncthreads();

    // ---- warp tiles ----
    const int warp_m = wid & 1;
    const int warp_n = wid >> 1;
    const bool isR = (warp_n >= 2);
    const int colTile = (warp_n & 1) * 64;

    const uint32_t aHiBase = sbase + OFF_AHI;
    const uint32_t aLoBase = sbase + OFF_ALO;
    const uint32_t bHiBase = sbase + (isR ? OFF_RHI : OFF_WHI);
    const uint32_t bLoBase = sbase + (isR ? OFF_RLO : OFF_WLO);

    const uint32_t aOff = (uint32_t)((warp_m * 64 + (lane & 15)) * TSTRIDE
                                     + ((lane >> 4) * 8) * 2);
    const int q = lane >> 3, r8 = lane & 7;
    const uint32_t bOff = (uint32_t)((colTile + ((q & 2) << 2) + r8) * TSTRIDE
                                     + ((q & 1) * 8) * 2);

    float c[4][8][4];
#pragma unroll
    for (int i = 0; i < 4; i++)
#pragma unroll
        for (int j = 0; j < 8; j++)
#pragma unroll
            for (int z = 0; z < 4; z++) c[i][j][z] = 0.f;

#pragma unroll 1
    for (int k0 = 0; k0 < 128; k0 += 16) {
        const uint32_t kB = (uint32_t)(k0 * 2);
#pragma unroll
        for (int term = 0; term < 3; term++) {
            const uint32_t aSel = (term == 2) ? aLoBase : aHiBase;
            const uint32_t bSel = (term == 1) ? bLoBase : bHiBase;
            uint32_t a[4][4];
#pragma unroll
            for (int mf = 0; mf < 4; mf++)
                ldm4(a[mf], aSel + aOff + mf * (16 * TSTRIDE) + kB);
#pragma unroll
            for (int nf2 = 0; nf2 < 4; nf2++) {
                uint32_t bb[4];
                ldm4(bb, bSel + bOff + nf2 * (16 * TSTRIDE) + kB);
#pragma unroll
                for (int mf = 0; mf < 4; mf++) {
                    mma16816(c[mf][nf2 * 2],     a[mf], bb[0], bb[1]);
                    mma16816(c[mf][nf2 * 2 + 1], a[mf], bb[2], bb[3]);
                }
            }
        }
    }

    // ---- epilogue ----
    const int g = lane >> 2, t = lane & 3;
    float* dst = isR ? fout : g_h;
    const int rowBase = row0 + warp_m * 64;
#pragma unroll
    for (int nf = 0; nf < 8; nf++) {
        const int col = colTile + nf * 8 + 2 * t;
        float bx = 0.f, by = 0.f;
        if (isR) {
            float2 bv = *(const float2*)(bias + col);
            bx = bv.x; by = bv.y;
        }
#pragma unroll
        for (int mf = 0; mf < 4; mf++) {
            int rlo = rowBase + mf * 16 + g;
            if (rlo < NN) {
                float2 o = make_float2(c[mf][nf][0] + bx, c[mf][nf][1] + by);
                *(float2*)(dst + rlo * 128 + col) = o;
            }
            if (rlo + 8 < NN) {
                float2 o = make_float2(c[mf][nf][2] + bx, c[mf][nf][3] + by);
                *(float2*)(dst + (rlo + 8) * 128 + col) = o;
            }
        }
    }
}

// ---------------- graph preprocessing --------------------------------------
__global__ void k_zero() {
    int i = blockIdx.x * blockDim.x + threadIdx.x;
    if (i < NN) { g_deg[i] = 0; g_fill[i] = 0; }
    if (i < NG*HH) g_pool[i] = 0.f;
    if (i < NG) g_cnt[i] = 0.f;
    if (i == 0) g_total = 0;
}

__global__ void k_deg(const int* __restrict__ ei) {
    int e = blockIdx.x * blockDim.x + threadIdx.x;
    if (e < NE) {
        int d = ei[NE + e];
        if (d >= 0 && d < NN) atomicAdd(&g_deg[d], 1);
    }
}

__global__ void k_dinv() {
    int i = blockIdx.x * blockDim.x + threadIdx.x;
    if (i < NN) {
        int d = g_deg[i];
        g_dinv[i] = (d > 0) ? rsqrtf((float)d) : 0.f;
    }
}

// per-block scan + one atomic per block (CSR segment order is irrelevant)
__global__ void k_off() {
    __shared__ int sh[256];
    __shared__ int base;
    const int t = threadIdx.x;
    const int i = blockIdx.x * 256 + t;
    int d = (i < NN) ? g_deg[i] : 0;
    sh[t] = d;
    __syncthreads();
    for (int off = 1; off < 256; off <<= 1) {
        int v = (t >= off) ? sh[t - off] : 0;
        __syncthreads();
        sh[t] += v;
        __syncthreads();
    }
    if (t == 255) base = atomicAdd(&g_total, sh[255]);
    __syncthreads();
    if (i < NN) g_beg[i] = base + sh[t] - d;
}

__global__ void k_fill(const int* __restrict__ ei) {
    int e = blockIdx.x * blockDim.x + threadIdx.x;
    if (e < NE) {
        int s = ei[e];
        int d = ei[NE + e];
        if (s < 0 || s >= NN || d < 0 || d >= NN) return;
        float w = g_dinv[s] * g_dinv[d];
        int pos = g_beg[d] + atomicAdd(&g_fill[d], 1);
        g_src[pos] = s;
        g_w[pos] = w;
    }
}

// ---------------- CSR aggregation: warp per node, 4x unrolled ---------------
__global__ void k_agg(int outSel) {
    float* f = selBuf(outSel);
    const int wid = threadIdx.x >> 5, lane = threadIdx.x & 31;
    const int i = blockIdx.x * 4 + wid;
    if (i >= NN) return;
    const int beg = g_beg[i], end = beg + g_deg[i];
    float4 acc = *(float4*)(f + i * HH + lane * 4);
    int e = beg;
    for (; e + 4 <= end; e += 4) {
        int s0 = g_src[e], s1 = g_src[e+1], s2 = g_src[e+2], s3 = g_src[e+3];
        float w0 = g_w[e], w1 = g_w[e+1], w2 = g_w[e+2], w3 = g_w[e+3];
        float4 h0 = *(const float4*)(g_h + s0 * HH + lane * 4);
        float4 h1 = *(const float4*)(g_h + s1 * HH + lane * 4);
        float4 h2 = *(const float4*)(g_h + s2 * HH + lane * 4);
        float4 h3 = *(const float4*)(g_h + s3 * HH + lane * 4);
        acc.x += h0.x*w0 + h1.x*w1 + h2.x*w2 + h3.x*w3;
        acc.y += h0.y*w0 + h1.y*w1 + h2.y*w2 + h3.y*w3;
        acc.z += h0.z*w0 + h1.z*w1 + h2.z*w2 + h3.z*w3;
        acc.w += h0.w*w0 + h1.w*w1 + h2.w*w2 + h3.w*w3;
    }
    for (; e < end; e++) {
        int s = g_src[e];
        float w = g_w[e];
        float4 hv = *(const float4*)(g_h + s * HH + lane * 4);
        acc.x += hv.x * w; acc.y += hv.y * w;
        acc.z += hv.z * w; acc.w += hv.w * w;
    }
    *(float4*)(f + i * HH + lane * 4) = acc;
}

// ---------------- relu + write `last` + mean-pool accumulation -------------
__global__ void k_pool(int inSel,
                       const int* __restrict__ batch,
                       float* __restrict__ lastOut) {
    const float* f = selBuf(inSel);
    const int t = threadIdx.x;
    const int base = blockIdx.x * 64;
    float acc = 0.f;
    int cur = -1;
    for (int r = 0; r < 64; r++) {
        int i = base + r;
        if (i >= NN) break;
        float v = fmaxf(f[i * HH + t], 0.f);
        lastOut[i * HH + t] = v;
        int bg = batch[i];
        if (bg != cur) {
            if (cur >= 0) atomicAdd(&g_pool[cur * HH + t], acc);
            cur = bg; acc = 0.f;
        }
        acc += v;
    }
    if (cur >= 0) atomicAdd(&g_pool[cur * HH + t], acc);
    if (t == 0) {
        int c = 0; int cb = -1;
        for (int r = 0; r < 64; r++) {
            int i = base + r;
            if (i >= NN) break;
            int bg = batch[i];
            if (bg != cb) {
                if (cb >= 0) atomicAdd(&g_cnt[cb], (float)c);
                cb = bg; c = 0;
            }
            c++;
        }
        if (cb >= 0) atomicAdd(&g_cnt[cb], (float)c);
    }
}

// ---------------- MLP head + log_softmax ------------------------------------
__global__ void k_head(const float* __restrict__ l1w, const float* __restrict__ l1b,
                       const float* __restrict__ l2w, const float* __restrict__ l2b,
                       float* __restrict__ out) {
    __shared__ float p[HH];
    __shared__ float gg[HH];
    __shared__ float lg[NC];
    const int g = blockIdx.x, t = threadIdx.x;
    float c = fmaxf(g_cnt[g], 1.f);
    p[t] = g_pool[g * HH + t] / c;
    __syncthreads();
    float a = l1b[t];
#pragma unroll 8
    for (int k = 0; k < HH; k++) a += p[k] * l1w[k * HH + t];
    gg[t] = fmaxf(a, 0.f);
    __syncthreads();
    if (t < NC) {
        float a2 = l2b[t];
        for (int k = 0; k < HH; k++) a2 += gg[k] * l2w[k * NC + t];
        lg[t] = a2;
    }
    __syncthreads();
    if (t < NC) {
        float m = lg[0];
        for (int j = 1; j < NC; j++) m = fmaxf(m, lg[j]);
        float s = 0.f;
        for (int j = 0; j < NC; j++) s += expf(lg[j] - m);
        out[g * NC + t] = lg[t] - m - logf(s);
    }
}

// ---------------- launch -----------------------------------------------------
extern "C" void kernel_launch(void* const* d_in, const int* in_sizes, int n_in,
                              void* d_out, int out_size) {
    const float* x     = (const float*)d_in[0];
    const int*   ei    = (const int*)d_in[1];
    const int*   batch = (const int*)d_in[2];
    const float* W1    = (const float*)d_in[3];
    const float* R1    = (const float*)d_in[4];
    const float* b1    = (const float*)d_in[5];
    const float* Wc    = (const float*)d_in[6];
    const float* Rc    = (const float*)d_in[7];
    const float* bc    = (const float*)d_in[8];
    const float* l1w   = (const float*)d_in[9];
    const float* l1b   = (const float*)d_in[10];
    const float* l2w   = (const float*)d_in[11];
    const float* l2b   = (const float*)d_in[12];
    float* out     = (float*)d_out;
    float* lastOut = out + NG * NC;   // tuple order: (log_softmax, last)

    cudaFuncSetAttribute(k_mmagemm, cudaFuncAttributeMaxDynamicSharedMemorySize, SM_TOTAL);

    // preprocessing: CSR + weight split
    k_zero<<<(NN + 255) / 256, 256>>>();
    k_deg <<<(NE + 255) / 256, 256>>>(ei);
    k_split<<<8, 256>>>(W1, R1, Wc, Rc);
    k_dinv<<<(NN + 255) / 256, 256>>>();
    k_off <<<(NN + 255) / 256, 256>>>();
    k_fill<<<(NE + 255) / 256, 256>>>(ei);

    // 4 GCS layers
    int inSel = -1;
    int outSel = 0;
    for (int l = 0; l < 4; l++) {
        const float* b = (l == 0) ? b1 : bc + (l - 1) * HH;
        k_mmagemm<<<NTILES, 256, SM_TOTAL>>>(x, inSel, outSel, l, b);
        k_agg<<<(NN + 3) / 4, 128>>>(outSel);
        inSel = outSel;
        outSel ^= 1;
    }

    k_pool<<<(NN + 63) / 64, 128>>>(inSel, batch, lastOut);
    k_head<<<NG, 128>>>(l1w, l1b, l2w, l2b, out);
}

// round 7
// speedup vs baseline: 3.1278x; 1.0578x over previous
#include <cuda_runtime.h>
#include <cuda_bf16.h>
#include <cstdint>

#define NN 50000
#define NE 600000
#define HH 128
#define NG 128
#define NC 10
#define NT64 782                    // ceil(50000/64)

// ---------------- tile geometry ----------------------------------------------
#define TSTRIDE 272                 // 128 bf16 (256B) + 16B pad -> ldmatrix conflict-free
#define TILE_B  (128 * TSTRIDE)     // 34816 bytes per 128x128 bf16 image

// ---------------- scratch (static device globals; no allocation) ------------
__device__ float g_h [NN*HH];
__device__ float g_f0[NN*HH];
__device__ float g_f1[NN*HH];
__device__ float g_w [NE];
__device__ int   g_src[NE];
__device__ int   g_deg [NN];
__device__ int   g_fill[NN];
__device__ int   g_beg [NN];
__device__ int   g_total;
__device__ float g_dinv[NN];
__device__ float g_pool[NG*HH];
__device__ float g_cnt [NG];
__device__ int   g_tick[8];         // [layer*2 + isR] ticket counters
// pre-split weight images: [layer][WHI,WLO,RHI,RLO][TILE_B bytes]
__device__ __align__(16) char g_wimg[4][4][TILE_B];

__device__ __forceinline__ float* selBuf(int s) { return s ? g_f1 : g_f0; }

__device__ __forceinline__ uint32_t s2u(const void* p) {
    uint32_t a;
    asm("{ .reg .u64 t; cvta.to.shared.u64 t, %1; cvt.u32.u64 %0, t; }"
        : "=r"(a) : "l"(p));
    return a;
}

// ---------------- GEMM SMEM layout (per CTA: 104448 B -> 2 CTA/SM) ----------
#define A2HI 0
#define A2LO 17408                  // 64*272
#define B2HI 34816
#define B2LO 69632
#define SM2_TOTAL 104448

__device__ __forceinline__ void ldm4(uint32_t* r, uint32_t addr) {
    asm volatile("ldmatrix.sync.aligned.m8n8.x4.shared.b16 {%0,%1,%2,%3}, [%4];"
                 : "=r"(r[0]), "=r"(r[1]), "=r"(r[2]), "=r"(r[3]) : "r"(addr));
}
__device__ __forceinline__ void mma16816(float* c, const uint32_t* a,
                                         uint32_t b0, uint32_t b1) {
    asm volatile(
        "mma.sync.aligned.m16n8k16.row.col.f32.bf16.bf16.f32 "
        "{%0,%1,%2,%3}, {%4,%5,%6,%7}, {%8,%9}, {%0,%1,%2,%3};"
        : "+f"(c[0]), "+f"(c[1]), "+f"(c[2]), "+f"(c[3])
        : "r"(a[0]), "r"(a[1]), "r"(a[2]), "r"(a[3]), "r"(b0), "r"(b1));
}

__device__ __forceinline__ uint32_t pack2(float a, float b) {
    __nv_bfloat16 x = __float2bfloat16(a);
    __nv_bfloat16 y = __float2bfloat16(b);
    return (uint32_t)*(unsigned short*)&x | ((uint32_t)*(unsigned short*)&y << 16);
}

// ---------------- weight pre-split ------------------------------------------
__global__ void k_split(const float* __restrict__ W1, const float* __restrict__ R1,
                        const float* __restrict__ Wc, const float* __restrict__ Rc) {
    const int layer = blockIdx.x >> 1;
    const int isR = blockIdx.x & 1;
    const float* src;
    if (layer == 0) src = isR ? R1 : W1;
    else src = (isR ? Rc : Wc) + (layer - 1) * HH * HH;
    char* hiB = g_wimg[layer][isR * 2];
    char* loB = g_wimg[layer][isR * 2 + 1];
    for (int idx = threadIdx.x; idx < HH * HH; idx += 256) {
        int n = idx >> 7, k = idx & 127;
        float v = src[k * HH + n];
        __nv_bfloat16 h = __float2bfloat16(v);
        __nv_bfloat16 l = __float2bfloat16(v - __bfloat162float(h));
        uint32_t bo = n * TSTRIDE + k * 2;
        *(unsigned short*)(hiB + bo) = *(unsigned short*)&h;
        *(unsigned short*)(loB + bo) = *(unsigned short*)&l;
    }
}

// ---------------- persistent dual GEMM via mma.sync --------------------------
// blockIdx.y==0: out = relu?(X)@W -> g_h (no bias)
// blockIdx.y==1: out = relu?(X)@R + bias -> selBuf(outSel)
__global__ void __launch_bounds__(128, 2) k_mmagemm(
    const float* __restrict__ Xext, int inSel, int outSel, int layer,
    const float* __restrict__ bias)
{
    extern __shared__ char smem[];
    const uint32_t sbase = s2u(smem);
    const int tid = threadIdx.x;
    const int wid = tid >> 5, lane = tid & 31;
    const int isR = blockIdx.y;
    const float* X = (inSel < 0) ? Xext : selBuf(inSel);
    const bool reluIn = (inSel >= 0);
    float* dst = isR ? selBuf(outSel) : g_h;

    __shared__ int s_tile;

    // ---- B images (hi+lo, 69632 B) loaded ONCE per persistent CTA ----
    {
        const float4* src = (const float4*)g_wimg[layer][isR * 2];
        float4* d4 = (float4*)(smem + B2HI);
#pragma unroll
        for (int it = 0; it < 34; it++)
            d4[it * 128 + tid] = src[it * 128 + tid];
    }

    // warp fragment address components (same mapping as validated R5 kernel)
    const int n0 = wid * 32;
    const uint32_t aOff = (uint32_t)((lane & 15) * TSTRIDE + (lane >> 4) * 16);
    const int q = lane >> 3, r8 = lane & 7;
    const uint32_t bOff = (uint32_t)((n0 + ((q & 2) << 2) + r8) * TSTRIDE
                                     + (q & 1) * 16);
    const uint32_t aHiB = sbase + A2HI, aLoB = sbase + A2LO;
    const uint32_t bHiB = sbase + B2HI, bLoB = sbase + B2LO;
    const int gq = lane >> 2, t4 = lane & 3;

    while (true) {
        if (tid == 0) s_tile = atomicAdd(&g_tick[layer * 2 + isR], 1);
        __syncthreads();               // broadcast ticket; protect A from prior readers
        const int tile = s_tile;
        if (tile >= NT64) break;
        const int row0 = tile * 64;

        // ---- A tile: 64x128 fp32 -> bf16 hi/lo ----
#pragma unroll
        for (int it = 0; it < 16; it++) {
            int idx = it * 128 + tid;      // 2048 float4 slots
            int m = idx >> 5;
            int c4 = (idx & 31) * 4;
            float4 v = make_float4(0.f, 0.f, 0.f, 0.f);
            int gr = row0 + m;
            if (gr < NN) v = *(const float4*)(X + gr * 128 + c4);
            if (reluIn) {
                v.x = fmaxf(v.x, 0.f); v.y = fmaxf(v.y, 0.f);
                v.z = fmaxf(v.z, 0.f); v.w = fmaxf(v.w, 0.f);
            }
            float hx = __bfloat162float(__float2bfloat16(v.x));
            float hy = __bfloat162float(__float2bfloat16(v.y));
            float hz = __bfloat162float(__float2bfloat16(v.z));
            float hw = __bfloat162float(__float2bfloat16(v.w));
            uint32_t bo = m * TSTRIDE + c4 * 2;
            *(uint32_t*)(smem + A2HI + bo)     = pack2(v.x, v.y);
            *(uint32_t*)(smem + A2HI + bo + 4) = pack2(v.z, v.w);
            *(uint32_t*)(smem + A2LO + bo)     = pack2(v.x - hx, v.y - hy);
            *(uint32_t*)(smem + A2LO + bo + 4) = pack2(v.z - hz, v.w - hw);
        }
        __syncthreads();

        // ---- mainloop: 3-term bf16 split, warp tile m64 x n32 ----
        float c[4][4][4];
#pragma unroll
        for (int i = 0; i < 4; i++)
#pragma unroll
            for (int j = 0; j < 4; j++)
#pragma unroll
                for (int z = 0; z < 4; z++) c[i][j][z] = 0.f;

#pragma unroll 1
        for (int k0 = 0; k0 < 128; k0 += 16) {
            const uint32_t kB = (uint32_t)(k0 * 2);
#pragma unroll
            for (int term = 0; term < 3; term++) {
                const uint32_t aSel = (term == 2) ? aLoB : aHiB;
                const uint32_t bSel = (term == 1) ? bLoB : bHiB;
                uint32_t a[4][4];
#pragma unroll
                for (int mf = 0; mf < 4; mf++)
                    ldm4(a[mf], aSel + aOff + mf * (16 * TSTRIDE) + kB);
#pragma unroll
                for (int nf2 = 0; nf2 < 2; nf2++) {
                    uint32_t bb[4];
                    ldm4(bb, bSel + bOff + nf2 * (16 * TSTRIDE) + kB);
#pragma unroll
                    for (int mf = 0; mf < 4; mf++) {
                        mma16816(c[mf][nf2 * 2],     a[mf], bb[0], bb[1]);
                        mma16816(c[mf][nf2 * 2 + 1], a[mf], bb[2], bb[3]);
                    }
                }
            }
        }

        // ---- epilogue ----
#pragma unroll
        for (int nf = 0; nf < 4; nf++) {
            const int col = n0 + nf * 8 + 2 * t4;
            float bx = 0.f, by = 0.f;
            if (isR) {
                float2 bv = *(const float2*)(bias + col);
                bx = bv.x; by = bv.y;
            }
#pragma unroll
            for (int mf = 0; mf < 4; mf++) {
                int rlo = row0 + mf * 16 + gq;
                if (rlo < NN) {
                    float2 o = make_float2(c[mf][nf][0] + bx, c[mf][nf][1] + by);
                    *(float2*)(dst + rlo * 128 + col) = o;
                }
                if (rlo + 8 < NN) {
                    float2 o = make_float2(c[mf][nf][2] + bx, c[mf][nf][3] + by);
                    *(float2*)(dst + (rlo + 8) * 128 + col) = o;
                }
            }
        }
        __syncthreads();               // all reads of A done before next overwrite
    }
}

// ---------------- graph preprocessing --------------------------------------
__global__ void k_zero() {
    int i = blockIdx.x * blockDim.x + threadIdx.x;
    if (i < NN) { g_deg[i] = 0; g_fill[i] = 0; }
    if (i < NG*HH) g_pool[i] = 0.f;
    if (i < NG) g_cnt[i] = 0.f;
    if (i < 8) g_tick[i] = 0;
    if (i == 0) g_total = 0;
}

__global__ void k_deg(const int* __restrict__ ei) {
    int e = blockIdx.x * blockDim.x + threadIdx.x;
    if (e < NE) {
        int d = ei[NE + e];
        if (d >= 0 && d < NN) atomicAdd(&g_deg[d], 1);
    }
}

// fused: dinv + per-block scan + one atomic per block
__global__ void k_off() {
    __shared__ int sh[256];
    __shared__ int base;
    const int t = threadIdx.x;
    const int i = blockIdx.x * 256 + t;
    int d = (i < NN) ? g_deg[i] : 0;
    if (i < NN) g_dinv[i] = (d > 0) ? rsqrtf((float)d) : 0.f;
    sh[t] = d;
    __syncthreads();
    for (int off = 1; off < 256; off <<= 1) {
        int v = (t >= off) ? sh[t - off] : 0;
        __syncthreads();
        sh[t] += v;
        __syncthreads();
    }
    if (t == 255) base = atomicAdd(&g_total, sh[255]);
    __syncthreads();
    if (i < NN) g_beg[i] = base + sh[t] - d;
}

__global__ void k_fill(const int* __restrict__ ei) {
    int e = blockIdx.x * blockDim.x + threadIdx.x;
    if (e < NE) {
        int s = ei[e];
        int d = ei[NE + e];
        if (s < 0 || s >= NN || d < 0 || d >= NN) return;
        float w = g_dinv[s] * g_dinv[d];
        int pos = g_beg[d] + atomicAdd(&g_fill[d], 1);
        g_src[pos] = s;
        g_w[pos] = w;
    }
}

// ---------------- CSR aggregation: warp per node, 4x unrolled ---------------
__global__ void k_agg(int outSel) {
    float* f = selBuf(outSel);
    const int wid = threadIdx.x >> 5, lane = threadIdx.x & 31;
    const int i = blockIdx.x * 4 + wid;
    if (i >= NN) return;
    const int beg = g_beg[i], end = beg + g_deg[i];
    float4 acc = *(float4*)(f + i * HH + lane * 4);
    int e = beg;
    for (; e + 4 <= end; e += 4) {
        int s0 = g_src[e], s1 = g_src[e+1], s2 = g_src[e+2], s3 = g_src[e+3];
        float w0 = g_w[e], w1 = g_w[e+1], w2 = g_w[e+2], w3 = g_w[e+3];
        float4 h0 = *(const float4*)(g_h + s0 * HH + lane * 4);
        float4 h1 = *(const float4*)(g_h + s1 * HH + lane * 4);
        float4 h2 = *(const float4*)(g_h + s2 * HH + lane * 4);
        float4 h3 = *(const float4*)(g_h + s3 * HH + lane * 4);
        acc.x += h0.x*w0 + h1.x*w1 + h2.x*w2 + h3.x*w3;
        acc.y += h0.y*w0 + h1.y*w1 + h2.y*w2 + h3.y*w3;
        acc.z += h0.z*w0 + h1.z*w1 + h2.z*w2 + h3.z*w3;
        acc.w += h0.w*w0 + h1.w*w1 + h2.w*w2 + h3.w*w3;
    }
    for (; e < end; e++) {
        int s = g_src[e];
        float w = g_w[e];
        float4 hv = *(const float4*)(g_h + s * HH + lane * 4);
        acc.x += hv.x * w; acc.y += hv.y * w;
        acc.z += hv.z * w; acc.w += hv.w * w;
    }
    *(float4*)(f + i * HH + lane * 4) = acc;
}

// ---------------- relu + write `last` + mean-pool accumulation -------------
__global__ void k_pool(int inSel,
                       const int* __restrict__ batch,
                       float* __restrict__ lastOut) {
    const float* f = selBuf(inSel);
    const int t = threadIdx.x;
    const int base = blockIdx.x * 64;
    float acc = 0.f;
    int cur = -1;
    for (int r = 0; r < 64; r++) {
        int i = base + r;
        if (i >= NN) break;
        float v = fmaxf(f[i * HH + t], 0.f);
        lastOut[i * HH + t] = v;
        int bg = batch[i];
        if (bg != cur) {
            if (cur >= 0) atomicAdd(&g_pool[cur * HH + t], acc);
            cur = bg; acc = 0.f;
        }
        acc += v;
    }
    if (cur >= 0) atomicAdd(&g_pool[cur * HH + t], acc);
    if (t == 0) {
        int c = 0; int cb = -1;
        for (int r = 0; r < 64; r++) {
            int i = base + r;
            if (i >= NN) break;
            int bg = batch[i];
            if (bg != cb) {
                if (cb >= 0) atomicAdd(&g_cnt[cb], (float)c);
                cb = bg; c = 0;
            }
            c++;
        }
        if (cb >= 0) atomicAdd(&g_cnt[cb], (float)c);
    }
}

// ---------------- MLP head + log_softmax ------------------------------------
__global__ void k_head(const float* __restrict__ l1w, const float* __restrict__ l1b,
                       const float* __restrict__ l2w, const float* __restrict__ l2b,
                       float* __restrict__ out) {
    __shared__ float p[HH];
    __shared__ float gg[HH];
    __shared__ float lg[NC];
    const int g = blockIdx.x, t = threadIdx.x;
    float c = fmaxf(g_cnt[g], 1.f);
    p[t] = g_pool[g * HH + t] / c;
    __syncthreads();
    float a = l1b[t];
#pragma unroll 8
    for (int k = 0; k < HH; k++) a += p[k] * l1w[k * HH + t];
    gg[t] = fmaxf(a, 0.f);
    __syncthreads();
    if (t < NC) {
        float a2 = l2b[t];
        for (int k = 0; k < HH; k++) a2 += gg[k] * l2w[k * NC + t];
        lg[t] = a2;
    }
    __syncthreads();
    if (t < NC) {
        float m = lg[0];
        for (int j = 1; j < NC; j++) m = fmaxf(m, lg[j]);
        float s = 0.f;
        for (int j = 0; j < NC; j++) s += expf(lg[j] - m);
        out[g * NC + t] = lg[t] - m - logf(s);
    }
}

// ---------------- launch -----------------------------------------------------
extern "C" void kernel_launch(void* const* d_in, const int* in_sizes, int n_in,
                              void* d_out, int out_size) {
    const float* x     = (const float*)d_in[0];
    const int*   ei    = (const int*)d_in[1];
    const int*   batch = (const int*)d_in[2];
    const float* W1    = (const float*)d_in[3];
    const float* R1    = (const float*)d_in[4];
    const float* b1    = (const float*)d_in[5];
    const float* Wc    = (const float*)d_in[6];
    const float* Rc    = (const float*)d_in[7];
    const float* bc    = (const float*)d_in[8];
    const float* l1w   = (const float*)d_in[9];
    const float* l1b   = (const float*)d_in[10];
    const float* l2w   = (const float*)d_in[11];
    const float* l2b   = (const float*)d_in[12];
    float* out     = (float*)d_out;
    float* lastOut = out + NG * NC;   // tuple order: (log_softmax, last)

    cudaFuncSetAttribute(k_mmagemm, cudaFuncAttributeMaxDynamicSharedMemorySize, SM2_TOTAL);

    // preprocessing: CSR + weight split
    k_zero<<<(NN + 255) / 256, 256>>>();
    k_deg <<<(NE + 255) / 256, 256>>>(ei);
    k_split<<<8, 256>>>(W1, R1, Wc, Rc);
    k_off <<<(NN + 255) / 256, 256>>>();
    k_fill<<<(NE + 255) / 256, 256>>>(ei);

    // 4 GCS layers
    int inSel = -1;
    int outSel = 0;
    for (int l = 0; l < 4; l++) {
        const float* b = (l == 0) ? b1 : bc + (l - 1) * HH;
        k_mmagemm<<<dim3(152, 2), 128, SM2_TOTAL>>>(x, inSel, outSel, l, b);
        k_agg<<<(NN + 3) / 4, 128>>>(outSel);
        inSel = outSel;
        outSel ^= 1;
    }

    k_pool<<<(NN + 63) / 64, 128>>>(inSel, batch, lastOut);
    k_head<<<NG, 128>>>(l1w, l1b, l2w, l2b, out);
}

// round 8
// speedup vs baseline: 3.2934x; 1.0529x over previous
#include <cuda_runtime.h>
#include <cuda_bf16.h>
#include <cstdint>

#define NN 50000
#define NE 600000
#define HH 128
#define NG 128
#define NC 10
#define NT64 782                    // ceil(50000/64)

// ---------------- tile geometry ----------------------------------------------
#define TSTRIDE 272                 // 128 bf16 (256B) + 16B pad -> ldmatrix conflict-free
#define TILE_B  (128 * TSTRIDE)     // 34816 bytes per 128x128 bf16 image

// ---------------- scratch (static device globals; no allocation) ------------
__device__ float g_h [NN*HH];
__device__ float g_f0[NN*HH];
__device__ float g_f1[NN*HH];
__device__ float g_w [NE];
__device__ int   g_src[NE];
__device__ int   g_deg [NN];
__device__ int   g_fill[NN];
__device__ int   g_beg [NN];
__device__ int   g_total;
__device__ float g_dinv[NN];
__device__ float g_pool[NG*HH];
__device__ float g_cnt [NG];
__device__ int   g_tick[8];         // [layer*2 + isR] ticket counters
// pre-split weight images: [layer][WHI,WLO,RHI,RLO][TILE_B bytes]
__device__ __align__(16) char g_wimg[4][4][TILE_B];

__device__ __forceinline__ float* selBuf(int s) { return s ? g_f1 : g_f0; }

__device__ __forceinline__ uint32_t s2u(const void* p) {
    uint32_t a;
    asm("{ .reg .u64 t; cvta.to.shared.u64 t, %1; cvt.u32.u64 %0, t; }"
        : "=r"(a) : "l"(p));
    return a;
}

// ---------------- GEMM SMEM layout (per CTA: 104448 B -> 2 CTA/SM) ----------
#define A2HI 0
#define A2LO 17408                  // 64*272
#define B2HI 34816
#define B2LO 69632
#define SM2_TOTAL 104448

__device__ __forceinline__ void ldm4(uint32_t* r, uint32_t addr) {
    asm volatile("ldmatrix.sync.aligned.m8n8.x4.shared.b16 {%0,%1,%2,%3}, [%4];"
                 : "=r"(r[0]), "=r"(r[1]), "=r"(r[2]), "=r"(r[3]) : "r"(addr));
}
__device__ __forceinline__ void mma16816(float* c, const uint32_t* a,
                                         uint32_t b0, uint32_t b1) {
    asm volatile(
        "mma.sync.aligned.m16n8k16.row.col.f32.bf16.bf16.f32 "
        "{%0,%1,%2,%3}, {%4,%5,%6,%7}, {%8,%9}, {%0,%1,%2,%3};"
        : "+f"(c[0]), "+f"(c[1]), "+f"(c[2]), "+f"(c[3])
        : "r"(a[0]), "r"(a[1]), "r"(a[2]), "r"(a[3]), "r"(b0), "r"(b1));
}

__device__ __forceinline__ uint32_t pack2(float a, float b) {
    __nv_bfloat16 x = __float2bfloat16(a);
    __nv_bfloat16 y = __float2bfloat16(b);
    return (uint32_t)*(unsigned short*)&x | ((uint32_t)*(unsigned short*)&y << 16);
}

// ---------------- fused: zero scratch + pre-split weights -------------------
// blocks [0,196): zero; blocks [196,204): split (layer, W/R)
__global__ void k_pre(const float* __restrict__ W1, const float* __restrict__ R1,
                      const float* __restrict__ Wc, const float* __restrict__ Rc) {
    if (blockIdx.x < 196) {
        int i = blockIdx.x * 256 + threadIdx.x;
        if (i < NN) { g_deg[i] = 0; g_fill[i] = 0; }
        if (i < NG*HH) g_pool[i] = 0.f;
        if (i < NG) g_cnt[i] = 0.f;
        if (i < 8) g_tick[i] = 0;
        if (i == 0) g_total = 0;
        return;
    }
    const int b = blockIdx.x - 196;
    const int layer = b >> 1;
    const int isR = b & 1;
    const float* src;
    if (layer == 0) src = isR ? R1 : W1;
    else src = (isR ? Rc : Wc) + (layer - 1) * HH * HH;
    char* hiB = g_wimg[layer][isR * 2];
    char* loB = g_wimg[layer][isR * 2 + 1];
    for (int idx = threadIdx.x; idx < HH * HH; idx += 256) {
        int n = idx >> 7, k = idx & 127;
        float v = src[k * HH + n];
        __nv_bfloat16 h = __float2bfloat16(v);
        __nv_bfloat16 l = __float2bfloat16(v - __bfloat162float(h));
        uint32_t bo = n * TSTRIDE + k * 2;
        *(unsigned short*)(hiB + bo) = *(unsigned short*)&h;
        *(unsigned short*)(loB + bo) = *(unsigned short*)&l;
    }
}

// ---------------- persistent dual GEMM via mma.sync --------------------------
// blockIdx.y==0: out = relu?(X)@W -> g_h (no bias)
// blockIdx.y==1: out = relu?(X)@R + bias -> selBuf(outSel)
// 256 threads, 8 warps: warp grid 2(m) x 4(n), warp tile m32 x n32
__global__ void __launch_bounds__(256, 2) k_mmagemm(
    const float* __restrict__ Xext, int inSel, int outSel, int layer,
    const float* __restrict__ bias)
{
    extern __shared__ char smem[];
    const uint32_t sbase = s2u(smem);
    const int tid = threadIdx.x;
    const int wid = tid >> 5, lane = tid & 31;
    const int isR = blockIdx.y;
    const float* X = (inSel < 0) ? Xext : selBuf(inSel);
    const bool reluIn = (inSel >= 0);
    float* dst = isR ? selBuf(outSel) : g_h;

    __shared__ int s_tile;

    // ---- B images (hi+lo, 69632 B) loaded ONCE per persistent CTA ----
    {
        const float4* src = (const float4*)g_wimg[layer][isR * 2];
        float4* d4 = (float4*)(smem + B2HI);
#pragma unroll
        for (int it = 0; it < 17; it++)
            d4[it * 256 + tid] = src[it * 256 + tid];
    }

    // warp decomposition
    const int wm = wid & 1;            // m-half (32 rows)
    const int wn = wid >> 1;           // n-quarter (32 cols)
    const int n0 = wn * 32;
    const uint32_t aOff = (uint32_t)((wm * 32 + (lane & 15)) * TSTRIDE
                                     + (lane >> 4) * 16);
    const int q = lane >> 3, r8 = lane & 7;
    const uint32_t bOff = (uint32_t)((n0 + ((q & 2) << 2) + r8) * TSTRIDE
                                     + (q & 1) * 16);
    const uint32_t aHiB = sbase + A2HI, aLoB = sbase + A2LO;
    const uint32_t bHiB = sbase + B2HI, bLoB = sbase + B2LO;
    const int gq = lane >> 2, t4 = lane & 3;

    // bias per thread (constant per layer), cols n0 + nf*8 + 2*t4
    float bx[4], by[4];
#pragma unroll
    for (int nf = 0; nf < 4; nf++) {
        if (isR) {
            float2 bv = *(const float2*)(bias + n0 + nf * 8 + 2 * t4);
            bx[nf] = bv.x; by[nf] = bv.y;
        } else { bx[nf] = 0.f; by[nf] = 0.f; }
    }

    while (true) {
        if (tid == 0) s_tile = atomicAdd(&g_tick[layer * 2 + isR], 1);
        __syncthreads();               // broadcast ticket; protect A from prior readers
        const int tile = s_tile;
        if (tile >= NT64) break;
        const int row0 = tile * 64;

        // ---- A tile: 64x128 fp32 -> bf16 hi/lo (8 iters over 256 threads) ----
#pragma unroll
        for (int it = 0; it < 8; it++) {
            int idx = it * 256 + tid;      // 2048 float4 slots
            int m = idx >> 5;
            int c4 = (idx & 31) * 4;
            float4 v = make_float4(0.f, 0.f, 0.f, 0.f);
            int gr = row0 + m;
            if (gr < NN) v = *(const float4*)(X + gr * 128 + c4);
            if (reluIn) {
                v.x = fmaxf(v.x, 0.f); v.y = fmaxf(v.y, 0.f);
                v.z = fmaxf(v.z, 0.f); v.w = fmaxf(v.w, 0.f);
            }
            float hx = __bfloat162float(__float2bfloat16(v.x));
            float hy = __bfloat162float(__float2bfloat16(v.y));
            float hz = __bfloat162float(__float2bfloat16(v.z));
            float hw = __bfloat162float(__float2bfloat16(v.w));
            uint32_t bo = m * TSTRIDE + c4 * 2;
            *(uint32_t*)(smem + A2HI + bo)     = pack2(v.x, v.y);
            *(uint32_t*)(smem + A2HI + bo + 4) = pack2(v.z, v.w);
            *(uint32_t*)(smem + A2LO + bo)     = pack2(v.x - hx, v.y - hy);
            *(uint32_t*)(smem + A2LO + bo + 4) = pack2(v.z - hz, v.w - hw);
        }
        __syncthreads();

        // ---- mainloop: 3-term bf16 split, warp tile m32 x n32 ----
        float c[2][4][4];
#pragma unroll
        for (int i = 0; i < 2; i++)
#pragma unroll
            for (int j = 0; j < 4; j++)
#pragma unroll
                for (int z = 0; z < 4; z++) c[i][j][z] = 0.f;

#pragma unroll 2
        for (int k0 = 0; k0 < 128; k0 += 16) {
            const uint32_t kB = (uint32_t)(k0 * 2);
#pragma unroll
            for (int term = 0; term < 3; term++) {
                const uint32_t aSel = (term == 2) ? aLoB : aHiB;
                const uint32_t bSel = (term == 1) ? bLoB : bHiB;
                uint32_t a[2][4];
#pragma unroll
                for (int mf = 0; mf < 2; mf++)
                    ldm4(a[mf], aSel + aOff + mf * (16 * TSTRIDE) + kB);
#pragma unroll
                for (int nf2 = 0; nf2 < 2; nf2++) {
                    uint32_t bb[4];
                    ldm4(bb, bSel + bOff + nf2 * (16 * TSTRIDE) + kB);
#pragma unroll
                    for (int mf = 0; mf < 2; mf++) {
                        mma16816(c[mf][nf2 * 2],     a[mf], bb[0], bb[1]);
                        mma16816(c[mf][nf2 * 2 + 1], a[mf], bb[2], bb[3]);
                    }
                }
            }
        }

        // ---- epilogue ----
#pragma unroll
        for (int nf = 0; nf < 4; nf++) {
            const int col = n0 + nf * 8 + 2 * t4;
#pragma unroll
            for (int mf = 0; mf < 2; mf++) {
                int rlo = row0 + wm * 32 + mf * 16 + gq;
                if (rlo < NN) {
                    float2 o = make_float2(c[mf][nf][0] + bx[nf], c[mf][nf][1] + by[nf]);
                    *(float2*)(dst + rlo * 128 + col) = o;
                }
                if (rlo + 8 < NN) {
                    float2 o = make_float2(c[mf][nf][2] + bx[nf], c[mf][nf][3] + by[nf]);
                    *(float2*)(dst + (rlo + 8) * 128 + col) = o;
                }
            }
        }
        __syncthreads();               // all reads of A done before next overwrite
    }
}

// ---------------- graph preprocessing --------------------------------------
__global__ void k_deg(const int* __restrict__ ei) {
    int e = blockIdx.x * blockDim.x + threadIdx.x;
    if (e < NE) {
        int d = ei[NE + e];
        if (d >= 0 && d < NN) atomicAdd(&g_deg[d], 1);
    }
}

// fused: dinv + per-block scan + one atomic per block
__global__ void k_off() {
    __shared__ int sh[256];
    __shared__ int base;
    const int t = threadIdx.x;
    const int i = blockIdx.x * 256 + t;
    int d = (i < NN) ? g_deg[i] : 0;
    if (i < NN) g_dinv[i] = (d > 0) ? rsqrtf((float)d) : 0.f;
    sh[t] = d;
    __syncthreads();
    for (int off = 1; off < 256; off <<= 1) {
        int v = (t >= off) ? sh[t - off] : 0;
        __syncthreads();
        sh[t] += v;
        __syncthreads();
    }
    if (t == 255) base = atomicAdd(&g_total, sh[255]);
    __syncthreads();
    if (i < NN) g_beg[i] = base + sh[t] - d;
}

__global__ void k_fill(const int* __restrict__ ei) {
    int e = blockIdx.x * blockDim.x + threadIdx.x;
    if (e < NE) {
        int s = ei[e];
        int d = ei[NE + e];
        if (s < 0 || s >= NN || d < 0 || d >= NN) return;
        float w = g_dinv[s] * g_dinv[d];
        int pos = g_beg[d] + atomicAdd(&g_fill[d], 1);
        g_src[pos] = s;
        g_w[pos] = w;
    }
}

// ---------------- CSR aggregation: warp per node, 4x unrolled ---------------
__global__ void k_agg(int outSel) {
    float* f = selBuf(outSel);
    const int wid = threadIdx.x >> 5, lane = threadIdx.x & 31;
    const int i = blockIdx.x * 4 + wid;
    if (i >= NN) return;
    const int beg = g_beg[i], end = beg + g_deg[i];
    float4 acc = *(float4*)(f + i * HH + lane * 4);
    int e = beg;
    for (; e + 4 <= end; e += 4) {
        int s0 = g_src[e], s1 = g_src[e+1], s2 = g_src[e+2], s3 = g_src[e+3];
        float w0 = g_w[e], w1 = g_w[e+1], w2 = g_w[e+2], w3 = g_w[e+3];
        float4 h0 = *(const float4*)(g_h + s0 * HH + lane * 4);
        float4 h1 = *(const float4*)(g_h + s1 * HH + lane * 4);
        float4 h2 = *(const float4*)(g_h + s2 * HH + lane * 4);
        float4 h3 = *(const float4*)(g_h + s3 * HH + lane * 4);
        acc.x += h0.x*w0 + h1.x*w1 + h2.x*w2 + h3.x*w3;
        acc.y += h0.y*w0 + h1.y*w1 + h2.y*w2 + h3.y*w3;
        acc.z += h0.z*w0 + h1.z*w1 + h2.z*w2 + h3.z*w3;
        acc.w += h0.w*w0 + h1.w*w1 + h2.w*w2 + h3.w*w3;
    }
    for (; e < end; e++) {
        int s = g_src[e];
        float w = g_w[e];
        float4 hv = *(const float4*)(g_h + s * HH + lane * 4);
        acc.x += hv.x * w; acc.y += hv.y * w;
        acc.z += hv.z * w; acc.w += hv.w * w;
    }
    *(float4*)(f + i * HH + lane * 4) = acc;
}

// ---------------- relu + write `last` + mean-pool accumulation -------------
__global__ void k_pool(int inSel,
                       const int* __restrict__ batch,
                       float* __restrict__ lastOut) {
    const float* f = selBuf(inSel);
    const int t = threadIdx.x;
    const int base = blockIdx.x * 64;
    float acc = 0.f;
    int cur = -1;
    for (int r = 0; r < 64; r++) {
        int i = base + r;
        if (i >= NN) break;
        float v = fmaxf(f[i * HH + t], 0.f);
        lastOut[i * HH + t] = v;
        int bg = batch[i];
        if (bg != cur) {
            if (cur >= 0) atomicAdd(&g_pool[cur * HH + t], acc);
            cur = bg; acc = 0.f;
        }
        acc += v;
    }
    if (cur >= 0) atomicAdd(&g_pool[cur * HH + t], acc);
    if (t == 0) {
        int c = 0; int cb = -1;
        for (int r = 0; r < 64; r++) {
            int i = base + r;
            if (i >= NN) break;
            int bg = batch[i];
            if (bg != cb) {
                if (cb >= 0) atomicAdd(&g_cnt[cb], (float)c);
                cb = bg; c = 0;
            }
            c++;
        }
        if (cb >= 0) atomicAdd(&g_cnt[cb], (float)c);
    }
}

// ---------------- MLP head + log_softmax ------------------------------------
__global__ void k_head(const float* __restrict__ l1w, const float* __restrict__ l1b,
                       const float* __restrict__ l2w, const float* __restrict__ l2b,
                       float* __restrict__ out) {
    __shared__ float p[HH];
    __shared__ float gg[HH];
    __shared__ float lg[NC];
    const int g = blockIdx.x, t = threadIdx.x;
    float c = fmaxf(g_cnt[g], 1.f);
    p[t] = g_pool[g * HH + t] / c;
    __syncthreads();
    float a = l1b[t];
#pragma unroll 8
    for (int k = 0; k < HH; k++) a += p[k] * l1w[k * HH + t];
    gg[t] = fmaxf(a, 0.f);
    __syncthreads();
    if (t < NC) {
        float a2 = l2b[t];
        for (int k = 0; k < HH; k++) a2 += gg[k] * l2w[k * NC + t];
        lg[t] = a2;
    }
    __syncthreads();
    if (t < NC) {
        float m = lg[0];
        for (int j = 1; j < NC; j++) m = fmaxf(m, lg[j]);
        float s = 0.f;
        for (int j = 0; j < NC; j++) s += expf(lg[j] - m);
        out[g * NC + t] = lg[t] - m - logf(s);
    }
}

// ---------------- launch -----------------------------------------------------
extern "C" void kernel_launch(void* const* d_in, const int* in_sizes, int n_in,
                              void* d_out, int out_size) {
    const float* x     = (const float*)d_in[0];
    const int*   ei    = (const int*)d_in[1];
    const int*   batch = (const int*)d_in[2];
    const float* W1    = (const float*)d_in[3];
    const float* R1    = (const float*)d_in[4];
    const float* b1    = (const float*)d_in[5];
    const float* Wc    = (const float*)d_in[6];
    const float* Rc    = (const float*)d_in[7];
    const float* bc    = (const float*)d_in[8];
    const float* l1w   = (const float*)d_in[9];
    const float* l1b   = (const float*)d_in[10];
    const float* l2w   = (const float*)d_in[11];
    const float* l2b   = (const float*)d_in[12];
    float* out     = (float*)d_out;
    float* lastOut = out + NG * NC;   // tuple order: (log_softmax, last)

    cudaFuncSetAttribute(k_mmagemm, cudaFuncAttributeMaxDynamicSharedMemorySize, SM2_TOTAL);

    // preprocessing: zero+weight split fused, then CSR build
    k_pre <<<204, 256>>>(W1, R1, Wc, Rc);
    k_deg <<<(NE + 255) / 256, 256>>>(ei);
    k_off <<<(NN + 255) / 256, 256>>>();
    k_fill<<<(NE + 255) / 256, 256>>>(ei);

    // 4 GCS layers
    int inSel = -1;
    int outSel = 0;
    for (int l = 0; l < 4; l++) {
        const float* b = (l == 0) ? b1 : bc + (l - 1) * HH;
        k_mmagemm<<<dim3(148, 2), 256, SM2_TOTAL>>>(x, inSel, outSel, l, b);
        k_agg<<<(NN + 3) / 4, 128>>>(outSel);
        inSel = outSel;
        outSel ^= 1;
    }

    k_pool<<<(NN + 63) / 64, 128>>>(inSel, batch, lastOut);
    k_head<<<NG, 128>>>(l1w, l1b, l2w, l2b, out);
}

// round 9
// speedup vs baseline: 3.2976x; 1.0013x over previous
#include <cuda_runtime.h>
#include <cuda_bf16.h>
#include <cstdint>

#define NN 50000
#define NE 600000
#define HH 128
#define NG 128
#define NC 10
#define NT64 782                    // ceil(50000/64)
#define GEMM_GRID 148

// ---------------- tile geometry ----------------------------------------------
#define TSTRIDE 272                 // 128 bf16 (256B) + 16B pad -> ldmatrix conflict-free
#define TILE_B  (128 * TSTRIDE)     // 34816 bytes per 128x128 bf16 image

// ---------------- scratch (static device globals; no allocation) ------------
__device__ float g_h [NN*HH];
__device__ float g_f0[NN*HH];
__device__ float g_f1[NN*HH];
__device__ float g_w [NE];
__device__ int   g_src[NE];
__device__ int   g_deg [NN];
__device__ int   g_fill[NN];
__device__ int   g_beg [NN];
__device__ int   g_total;
__device__ float g_dinv[NN];
__device__ float g_pool[NG*HH];
__device__ float g_cnt [NG];
// pre-split weight images: [layer][WHI,WLO,RHI,RLO][TILE_B bytes]
__device__ __align__(16) char g_wimg[4][4][TILE_B];

__device__ __forceinline__ float* selBuf(int s) { return s ? g_f1 : g_f0; }

__device__ __forceinline__ uint32_t s2u(const void* p) {
    uint32_t a;
    asm("{ .reg .u64 t; cvta.to.shared.u64 t, %1; cvt.u32.u64 %0, t; }"
        : "=r"(a) : "l"(p));
    return a;
}

// ---------------- GEMM SMEM layout (per CTA: 104448 B -> 2 CTA/SM) ----------
#define A2HI 0
#define A2LO 17408                  // 64*272
#define B2HI 34816
#define B2LO 69632
#define SM2_TOTAL 104448

__device__ __forceinline__ void ldm4(uint32_t* r, uint32_t addr) {
    asm volatile("ldmatrix.sync.aligned.m8n8.x4.shared.b16 {%0,%1,%2,%3}, [%4];"
                 : "=r"(r[0]), "=r"(r[1]), "=r"(r[2]), "=r"(r[3]) : "r"(addr));
}
__device__ __forceinline__ void mma16816(float* c, const uint32_t* a,
                                         uint32_t b0, uint32_t b1) {
    asm volatile(
        "mma.sync.aligned.m16n8k16.row.col.f32.bf16.bf16.f32 "
        "{%0,%1,%2,%3}, {%4,%5,%6,%7}, {%8,%9}, {%0,%1,%2,%3};"
        : "+f"(c[0]), "+f"(c[1]), "+f"(c[2]), "+f"(c[3])
        : "r"(a[0]), "r"(a[1]), "r"(a[2]), "r"(a[3]), "r"(b0), "r"(b1));
}

__device__ __forceinline__ uint32_t pack2(float a, float b) {
    __nv_bfloat16 x = __float2bfloat16(a);
    __nv_bfloat16 y = __float2bfloat16(b);
    return (uint32_t)*(unsigned short*)&x | ((uint32_t)*(unsigned short*)&y << 16);
}

// ---------------- fused: zero scratch + pre-split weights -------------------
__global__ void k_pre(const float* __restrict__ W1, const float* __restrict__ R1,
                      const float* __restrict__ Wc, const float* __restrict__ Rc) {
    if (blockIdx.x < 196) {
        int i = blockIdx.x * 256 + threadIdx.x;
        if (i < NN) { g_deg[i] = 0; g_fill[i] = 0; }
        if (i < NG*HH) g_pool[i] = 0.f;
        if (i < NG) g_cnt[i] = 0.f;
        if (i == 0) g_total = 0;
        return;
    }
    const int b = blockIdx.x - 196;
    const int layer = b >> 1;
    const int isR = b & 1;
    const float* src;
    if (layer == 0) src = isR ? R1 : W1;
    else src = (isR ? Rc : Wc) + (layer - 1) * HH * HH;
    char* hiB = g_wimg[layer][isR * 2];
    char* loB = g_wimg[layer][isR * 2 + 1];
    for (int idx = threadIdx.x; idx < HH * HH; idx += 256) {
        int n = idx >> 7, k = idx & 127;
        float v = src[k * HH + n];
        __nv_bfloat16 h = __float2bfloat16(v);
        __nv_bfloat16 l = __float2bfloat16(v - __bfloat162float(h));
        uint32_t bo = n * TSTRIDE + k * 2;
        *(unsigned short*)(hiB + bo) = *(unsigned short*)&h;
        *(unsigned short*)(loB + bo) = *(unsigned short*)&l;
    }
}

// ---------------- persistent dual GEMM via mma.sync --------------------------
// blockIdx.y==0: out = relu?(X)@W -> g_h (no bias)
// blockIdx.y==1: out = relu?(X)@R + bias -> selBuf(outSel)
// 256 threads, 8 warps: warp grid 2(m) x 4(n), warp tile m32 x n32
// Fixed strided tile schedule + register prefetch of next A tile.
__global__ void __launch_bounds__(256, 2) k_mmagemm(
    const float* __restrict__ Xext, int inSel, int outSel, int layer,
    const float* __restrict__ bias)
{
    extern __shared__ char smem[];
    const uint32_t sbase = s2u(smem);
    const int tid = threadIdx.x;
    const int wid = tid >> 5, lane = tid & 31;
    const int isR = blockIdx.y;
    const float* X = (inSel < 0) ? Xext : selBuf(inSel);
    const bool reluIn = (inSel >= 0);
    float* dst = isR ? selBuf(outSel) : g_h;

    // ---- B images (hi+lo, 69632 B) loaded ONCE per persistent CTA ----
    {
        const float4* src = (const float4*)g_wimg[layer][isR * 2];
        float4* d4 = (float4*)(smem + B2HI);
#pragma unroll
        for (int it = 0; it < 17; it++)
            d4[it * 256 + tid] = src[it * 256 + tid];
    }

    // warp decomposition
    const int wm = wid & 1;
    const int wn = wid >> 1;
    const int n0 = wn * 32;
    const uint32_t aOff = (uint32_t)((wm * 32 + (lane & 15)) * TSTRIDE
                                     + (lane >> 4) * 16);
    const int q = lane >> 3, r8 = lane & 7;
    const uint32_t bOff = (uint32_t)((n0 + ((q & 2) << 2) + r8) * TSTRIDE
                                     + (q & 1) * 16);
    const uint32_t aHiB = sbase + A2HI, aLoB = sbase + A2LO;
    const uint32_t bHiB = sbase + B2HI, bLoB = sbase + B2LO;
    const int gq = lane >> 2, t4 = lane & 3;

    float bx[4], by[4];
#pragma unroll
    for (int nf = 0; nf < 4; nf++) {
        if (isR) {
            float2 bv = *(const float2*)(bias + n0 + nf * 8 + 2 * t4);
            bx[nf] = bv.x; by[nf] = bv.y;
        } else { bx[nf] = 0.f; by[nf] = 0.f; }
    }

    // per-thread A-load geometry: 8 float4 per tile
    const int lm = tid >> 5;               // base row within tile: rows lm + it*8
    const int lc4 = (tid & 31) * 4;        // col

    float4 v[8];
    int tile = blockIdx.x;
    // prefetch first tile
    {
        const int row0 = tile * 64;
#pragma unroll
        for (int it = 0; it < 8; it++) {
            int gr = row0 + lm + it * 8;
            v[it] = (gr < NN) ? *(const float4*)(X + gr * 128 + lc4)
                              : make_float4(0.f, 0.f, 0.f, 0.f);
        }
    }

    while (tile < NT64) {
        const int row0 = tile * 64;
        const int next = tile + GEMM_GRID;

        __syncthreads();   // previous mainloop done reading A buffers
        // ---- convert prefetched regs -> SMEM hi/lo ----
#pragma unroll
        for (int it = 0; it < 8; it++) {
            float4 w = v[it];
            if (reluIn) {
                w.x = fmaxf(w.x, 0.f); w.y = fmaxf(w.y, 0.f);
                w.z = fmaxf(w.z, 0.f); w.w = fmaxf(w.w, 0.f);
            }
            float hx = __bfloat162float(__float2bfloat16(w.x));
            float hy = __bfloat162float(__float2bfloat16(w.y));
            float hz = __bfloat162float(__float2bfloat16(w.z));
            float hw = __bfloat162float(__float2bfloat16(w.w));
            uint32_t bo = (lm + it * 8) * TSTRIDE + lc4 * 2;
            *(uint32_t*)(smem + A2HI + bo)     = pack2(w.x, w.y);
            *(uint32_t*)(smem + A2HI + bo + 4) = pack2(w.z, w.w);
            *(uint32_t*)(smem + A2LO + bo)     = pack2(w.x - hx, w.y - hy);
            *(uint32_t*)(smem + A2LO + bo + 4) = pack2(w.z - hz, w.w - hw);
        }
        // ---- issue next tile's LDGs (hidden under mainloop) ----
        if (next < NT64) {
            const int nrow0 = next * 64;
#pragma unroll
            for (int it = 0; it < 8; it++) {
                int gr = nrow0 + lm + it * 8;
                v[it] = (gr < NN) ? *(const float4*)(X + gr * 128 + lc4)
                                  : make_float4(0.f, 0.f, 0.f, 0.f);
            }
        }
        __syncthreads();   // A buffers ready

        // ---- mainloop: 3-term bf16 split, warp tile m32 x n32 ----
        float c[2][4][4];
#pragma unroll
        for (int i = 0; i < 2; i++)
#pragma unroll
            for (int j = 0; j < 4; j++)
#pragma unroll
                for (int z = 0; z < 4; z++) c[i][j][z] = 0.f;

#pragma unroll 2
        for (int k0 = 0; k0 < 128; k0 += 16) {
            const uint32_t kB = (uint32_t)(k0 * 2);
#pragma unroll
            for (int term = 0; term < 3; term++) {
                const uint32_t aSel = (term == 2) ? aLoB : aHiB;
                const uint32_t bSel = (term == 1) ? bLoB : bHiB;
                uint32_t a[2][4];
#pragma unroll
                for (int mf = 0; mf < 2; mf++)
                    ldm4(a[mf], aSel + aOff + mf * (16 * TSTRIDE) + kB);
#pragma unroll
                for (int nf2 = 0; nf2 < 2; nf2++) {
                    uint32_t bb[4];
                    ldm4(bb, bSel + bOff + nf2 * (16 * TSTRIDE) + kB);
#pragma unroll
                    for (int mf = 0; mf < 2; mf++) {
                        mma16816(c[mf][nf2 * 2],     a[mf], bb[0], bb[1]);
                        mma16816(c[mf][nf2 * 2 + 1], a[mf], bb[2], bb[3]);
                    }
                }
            }
        }

        // ---- epilogue ----
#pragma unroll
        for (int nf = 0; nf < 4; nf++) {
            const int col = n0 + nf * 8 + 2 * t4;
#pragma unroll
            for (int mf = 0; mf < 2; mf++) {
                int rlo = row0 + wm * 32 + mf * 16 + gq;
                if (rlo < NN) {
                    float2 o = make_float2(c[mf][nf][0] + bx[nf], c[mf][nf][1] + by[nf]);
                    *(float2*)(dst + rlo * 128 + col) = o;
                }
                if (rlo + 8 < NN) {
                    float2 o = make_float2(c[mf][nf][2] + bx[nf], c[mf][nf][3] + by[nf]);
                    *(float2*)(dst + (rlo + 8) * 128 + col) = o;
                }
            }
        }
        tile = next;
    }
}

// ---------------- graph preprocessing --------------------------------------
__global__ void k_deg(const int* __restrict__ ei) {
    int e = blockIdx.x * blockDim.x + threadIdx.x;
    if (e < NE) {
        int d = ei[NE + e];
        if (d >= 0 && d < NN) atomicAdd(&g_deg[d], 1);
    }
}

__global__ void k_off() {
    __shared__ int sh[256];
    __shared__ int base;
    const int t = threadIdx.x;
    const int i = blockIdx.x * 256 + t;
    int d = (i < NN) ? g_deg[i] : 0;
    if (i < NN) g_dinv[i] = (d > 0) ? rsqrtf((float)d) : 0.f;
    sh[t] = d;
    __syncthreads();
    for (int off = 1; off < 256; off <<= 1) {
        int v = (t >= off) ? sh[t - off] : 0;
        __syncthreads();
        sh[t] += v;
        __syncthreads();
    }
    if (t == 255) base = atomicAdd(&g_total, sh[255]);
    __syncthreads();
    if (i < NN) g_beg[i] = base + sh[t] - d;
}

__global__ void k_fill(const int* __restrict__ ei) {
    int e = blockIdx.x * blockDim.x + threadIdx.x;
    if (e < NE) {
        int s = ei[e];
        int d = ei[NE + e];
        if (s < 0 || s >= NN || d < 0 || d >= NN) return;
        float w = g_dinv[s] * g_dinv[d];
        int pos = g_beg[d] + atomicAdd(&g_fill[d], 1);
        g_src[pos] = s;
        g_w[pos] = w;
    }
}

// ---------------- CSR aggregation: warp per node, 4x unrolled ---------------
// last!=0: apply relu and write to lastOut instead of f
__global__ void k_agg(int outSel, int last, float* __restrict__ lastOut) {
    float* f = selBuf(outSel);
    const int wid = threadIdx.x >> 5, lane = threadIdx.x & 31;
    const int i = blockIdx.x * 4 + wid;
    if (i >= NN) return;
    const int beg = g_beg[i], end = beg + g_deg[i];
    float4 acc = *(float4*)(f + i * HH + lane * 4);
    int e = beg;
    for (; e + 4 <= end; e += 4) {
        int s0 = g_src[e], s1 = g_src[e+1], s2 = g_src[e+2], s3 = g_src[e+3];
        float w0 = g_w[e], w1 = g_w[e+1], w2 = g_w[e+2], w3 = g_w[e+3];
        float4 h0 = *(const float4*)(g_h + s0 * HH + lane * 4);
        float4 h1 = *(const float4*)(g_h + s1 * HH + lane * 4);
        float4 h2 = *(const float4*)(g_h + s2 * HH + lane * 4);
        float4 h3 = *(const float4*)(g_h + s3 * HH + lane * 4);
        acc.x += h0.x*w0 + h1.x*w1 + h2.x*w2 + h3.x*w3;
        acc.y += h0.y*w0 + h1.y*w1 + h2.y*w2 + h3.y*w3;
        acc.z += h0.z*w0 + h1.z*w1 + h2.z*w2 + h3.z*w3;
        acc.w += h0.w*w0 + h1.w*w1 + h2.w*w2 + h3.w*w3;
    }
    for (; e < end; e++) {
        int s = g_src[e];
        float w = g_w[e];
        float4 hv = *(const float4*)(g_h + s * HH + lane * 4);
        acc.x += hv.x * w; acc.y += hv.y * w;
        acc.z += hv.z * w; acc.w += hv.w * w;
    }
    if (last) {
        acc.x = fmaxf(acc.x, 0.f); acc.y = fmaxf(acc.y, 0.f);
        acc.z = fmaxf(acc.z, 0.f); acc.w = fmaxf(acc.w, 0.f);
        *(float4*)(lastOut + i * HH + lane * 4) = acc;
    } else {
        *(float4*)(f + i * HH + lane * 4) = acc;
    }
}

// ---------------- mean-pool accumulation (input already relu'd) -------------
__global__ void k_pool(const float* __restrict__ f,
                       const int* __restrict__ batch) {
    const int t = threadIdx.x;
    const int base = blockIdx.x * 64;
    float acc = 0.f;
    int cur = -1;
    for (int r = 0; r < 64; r++) {
        int i = base + r;
        if (i >= NN) break;
        float v = f[i * HH + t];
        int bg = batch[i];
        if (bg != cur) {
            if (cur >= 0) atomicAdd(&g_pool[cur * HH + t], acc);
            cur = bg; acc = 0.f;
        }
        acc += v;
    }
    if (cur >= 0) atomicAdd(&g_pool[cur * HH + t], acc);
    if (t == 0) {
        int c = 0; int cb = -1;
        for (int r = 0; r < 64; r++) {
            int i = base + r;
            if (i >= NN) break;
            int bg = batch[i];
            if (bg != cb) {
                if (cb >= 0) atomicAdd(&g_cnt[cb], (float)c);
                cb = bg; c = 0;
            }
            c++;
        }
        if (cb >= 0) atomicAdd(&g_cnt[cb], (float)c);
    }
}

// ---------------- MLP head + log_softmax ------------------------------------
__global__ void k_head(const float* __restrict__ l1w, const float* __restrict__ l1b,
                       const float* __restrict__ l2w, const float* __restrict__ l2b,
                       float* __restrict__ out) {
    __shared__ float p[HH];
    __shared__ float gg[HH];
    __shared__ float lg[NC];
    const int g = blockIdx.x, t = threadIdx.x;
    float c = fmaxf(g_cnt[g], 1.f);
    p[t] = g_pool[g * HH + t] / c;
    __syncthreads();
    float a = l1b[t];
#pragma unroll 8
    for (int k = 0; k < HH; k++) a += p[k] * l1w[k * HH + t];
    gg[t] = fmaxf(a, 0.f);
    __syncthreads();
    if (t < NC) {
        float a2 = l2b[t];
        for (int k = 0; k < HH; k++) a2 += gg[k] * l2w[k * NC + t];
        lg[t] = a2;
    }
    __syncthreads();
    if (t < NC) {
        float m = lg[0];
        for (int j = 1; j < NC; j++) m = fmaxf(m, lg[j]);
        float s = 0.f;
        for (int j = 0; j < NC; j++) s += expf(lg[j] - m);
        out[g * NC + t] = lg[t] - m - logf(s);
    }
}

// ---------------- launch -----------------------------------------------------
extern "C" void kernel_launch(void* const* d_in, const int* in_sizes, int n_in,
                              void* d_out, int out_size) {
    const float* x     = (const float*)d_in[0];
    const int*   ei    = (const int*)d_in[1];
    const int*   batch = (const int*)d_in[2];
    const float* W1    = (const float*)d_in[3];
    const float* R1    = (const float*)d_in[4];
    const float* b1    = (const float*)d_in[5];
    const float* Wc    = (const float*)d_in[6];
    const float* Rc    = (const float*)d_in[7];
    const float* bc    = (const float*)d_in[8];
    const float* l1w   = (const float*)d_in[9];
    const float* l1b   = (const float*)d_in[10];
    const float* l2w   = (const float*)d_in[11];
    const float* l2b   = (const float*)d_in[12];
    float* out     = (float*)d_out;
    float* lastOut = out + NG * NC;   // tuple order: (log_softmax, last)

    cudaFuncSetAttribute(k_mmagemm, cudaFuncAttributeMaxDynamicSharedMemorySize, SM2_TOTAL);

    // preprocessing: zero+weight split fused, then CSR build
    k_pre <<<204, 256>>>(W1, R1, Wc, Rc);
    k_deg <<<(NE + 255) / 256, 256>>>(ei);
    k_off <<<(NN + 255) / 256, 256>>>();
    k_fill<<<(NE + 255) / 256, 256>>>(ei);

    // 4 GCS layers; last agg writes relu'd output straight into lastOut
    int inSel = -1;
    int outSel = 0;
    for (int l = 0; l < 4; l++) {
        const float* b = (l == 0) ? b1 : bc + (l - 1) * HH;
        k_mmagemm<<<dim3(GEMM_GRID, 2), 256, SM2_TOTAL>>>(x, inSel, outSel, l, b);
        k_agg<<<(NN + 3) / 4, 128>>>(outSel, (l == 3) ? 1 : 0, lastOut);
        inSel = outSel;
        outSel ^= 1;
    }

    k_pool<<<(NN + 63) / 64, 128>>>(lastOut, batch);
    k_head<<<NG, 128>>>(l1w, l1b, l2w, l2b, out);
}

// round 10
// speedup vs baseline: 3.4928x; 1.0592x over previous
#include <cuda_runtime.h>
#include <cuda_bf16.h>
#include <cuda_fp16.h>
#include <cstdint>

#define NN 50000
#define NE 600000
#define HH 128
#define NG 128
#define NC 10
#define NT64 782                    // ceil(50000/64)
#define GEMM_GRID 148

// ---------------- tile geometry ----------------------------------------------
#define TSTRIDE 272                 // 128 bf16 (256B) + 16B pad -> ldmatrix conflict-free
#define TILE_B  (128 * TSTRIDE)     // 34816 bytes per 128x128 bf16 image

// ---------------- scratch (static device globals; no allocation) ------------
__device__ __half g_h [NN*HH];     // W-path output, fp16 (gather bandwidth!)
__device__ float g_f0[NN*HH];
__device__ float g_f1[NN*HH];
__device__ float g_w [NE];
__device__ int   g_src[NE];
__device__ int   g_deg [NN];
__device__ int   g_beg [NN];       // after k_fill: END of each segment
__device__ int   g_total;
__device__ float g_dinv[NN];
__device__ float g_pool[NG*HH];
__device__ float g_cnt [NG];
// pre-split weight images: [layer][WHI,WLO,RHI,RLO][TILE_B bytes]
__device__ __align__(16) char g_wimg[4][4][TILE_B];

__device__ __forceinline__ float* selBuf(int s) { return s ? g_f1 : g_f0; }

__device__ __forceinline__ uint32_t s2u(const void* p) {
    uint32_t a;
    asm("{ .reg .u64 t; cvta.to.shared.u64 t, %1; cvt.u32.u64 %0, t; }"
        : "=r"(a) : "l"(p));
    return a;
}

// ---------------- GEMM SMEM layout (per CTA: 104448 B -> 2 CTA/SM) ----------
#define A2HI 0
#define A2LO 17408                  // 64*272
#define B2HI 34816
#define B2LO 69632
#define SM2_TOTAL 104448

__device__ __forceinline__ void ldm4(uint32_t* r, uint32_t addr) {
    asm volatile("ldmatrix.sync.aligned.m8n8.x4.shared.b16 {%0,%1,%2,%3}, [%4];"
                 : "=r"(r[0]), "=r"(r[1]), "=r"(r[2]), "=r"(r[3]) : "r"(addr));
}
__device__ __forceinline__ void mma16816(float* c, const uint32_t* a,
                                         uint32_t b0, uint32_t b1) {
    asm volatile(
        "mma.sync.aligned.m16n8k16.row.col.f32.bf16.bf16.f32 "
        "{%0,%1,%2,%3}, {%4,%5,%6,%7}, {%8,%9}, {%0,%1,%2,%3};"
        : "+f"(c[0]), "+f"(c[1]), "+f"(c[2]), "+f"(c[3])
        : "r"(a[0]), "r"(a[1]), "r"(a[2]), "r"(a[3]), "r"(b0), "r"(b1));
}

__device__ __forceinline__ uint32_t pack2(float a, float b) {
    __nv_bfloat16 x = __float2bfloat16(a);
    __nv_bfloat16 y = __float2bfloat16(b);
    return (uint32_t)*(unsigned short*)&x | ((uint32_t)*(unsigned short*)&y << 16);
}

// ---------------- fused: zero scratch + pre-split weights -------------------
__global__ void k_pre(const float* __restrict__ W1, const float* __restrict__ R1,
                      const float* __restrict__ Wc, const float* __restrict__ Rc) {
    if (blockIdx.x < 196) {
        int i = blockIdx.x * 256 + threadIdx.x;
        if (i < NN) g_deg[i] = 0;
        if (i < NG*HH) g_pool[i] = 0.f;
        if (i < NG) g_cnt[i] = 0.f;
        if (i == 0) g_total = 0;
        return;
    }
    const int b = blockIdx.x - 196;
    const int layer = b >> 1;
    const int isR = b & 1;
    const float* src;
    if (layer == 0) src = isR ? R1 : W1;
    else src = (isR ? Rc : Wc) + (layer - 1) * HH * HH;
    char* hiB = g_wimg[layer][isR * 2];
    char* loB = g_wimg[layer][isR * 2 + 1];
    for (int idx = threadIdx.x; idx < HH * HH; idx += 256) {
        int n = idx >> 7, k = idx & 127;
        float v = src[k * HH + n];
        __nv_bfloat16 h = __float2bfloat16(v);
        __nv_bfloat16 l = __float2bfloat16(v - __bfloat162float(h));
        uint32_t bo = n * TSTRIDE + k * 2;
        *(unsigned short*)(hiB + bo) = *(unsigned short*)&h;
        *(unsigned short*)(loB + bo) = *(unsigned short*)&l;
    }
}

// ---------------- persistent dual GEMM via mma.sync --------------------------
// blockIdx.y==0: out = relu?(X)@W -> g_h (fp16, no bias)
// blockIdx.y==1: out = relu?(X)@R + bias -> selBuf(outSel) (fp32)
__global__ void __launch_bounds__(256, 2) k_mmagemm(
    const float* __restrict__ Xext, int inSel, int outSel, int layer,
    const float* __restrict__ bias)
{
    extern __shared__ char smem[];
    const uint32_t sbase = s2u(smem);
    const int tid = threadIdx.x;
    const int wid = tid >> 5, lane = tid & 31;
    const int isR = blockIdx.y;
    const float* X = (inSel < 0) ? Xext : selBuf(inSel);
    const bool reluIn = (inSel >= 0);
    float* dstF = selBuf(outSel);

    // ---- B images (hi+lo, 69632 B) loaded ONCE per persistent CTA ----
    {
        const float4* src = (const float4*)g_wimg[layer][isR * 2];
        float4* d4 = (float4*)(smem + B2HI);
#pragma unroll
        for (int it = 0; it < 17; it++)
            d4[it * 256 + tid] = src[it * 256 + tid];
    }

    // warp decomposition
    const int wm = wid & 1;
    const int wn = wid >> 1;
    const int n0 = wn * 32;
    const uint32_t aOff = (uint32_t)((wm * 32 + (lane & 15)) * TSTRIDE
                                     + (lane >> 4) * 16);
    const int q = lane >> 3, r8 = lane & 7;
    const uint32_t bOff = (uint32_t)((n0 + ((q & 2) << 2) + r8) * TSTRIDE
                                     + (q & 1) * 16);
    const uint32_t aHiB = sbase + A2HI, aLoB = sbase + A2LO;
    const uint32_t bHiB = sbase + B2HI, bLoB = sbase + B2LO;
    const int gq = lane >> 2, t4 = lane & 3;

    float bx[4], by[4];
#pragma unroll
    for (int nf = 0; nf < 4; nf++) {
        if (isR) {
            float2 bv = *(const float2*)(bias + n0 + nf * 8 + 2 * t4);
            bx[nf] = bv.x; by[nf] = bv.y;
        } else { bx[nf] = 0.f; by[nf] = 0.f; }
    }

    const int lm = tid >> 5;
    const int lc4 = (tid & 31) * 4;

    float4 v[8];
    int tile = blockIdx.x;
    {
        const int row0 = tile * 64;
#pragma unroll
        for (int it = 0; it < 8; it++) {
            int gr = row0 + lm + it * 8;
            v[it] = (gr < NN) ? *(const float4*)(X + gr * 128 + lc4)
                              : make_float4(0.f, 0.f, 0.f, 0.f);
        }
    }

    while (tile < NT64) {
        const int row0 = tile * 64;
        const int next = tile + GEMM_GRID;

        __syncthreads();
#pragma unroll
        for (int it = 0; it < 8; it++) {
            float4 w = v[it];
            if (reluIn) {
                w.x = fmaxf(w.x, 0.f); w.y = fmaxf(w.y, 0.f);
                w.z = fmaxf(w.z, 0.f); w.w = fmaxf(w.w, 0.f);
            }
            float hx = __bfloat162float(__float2bfloat16(w.x));
            float hy = __bfloat162float(__float2bfloat16(w.y));
            float hz = __bfloat162float(__float2bfloat16(w.z));
            float hw = __bfloat162float(__float2bfloat16(w.w));
            uint32_t bo = (lm + it * 8) * TSTRIDE + lc4 * 2;
            *(uint32_t*)(smem + A2HI + bo)     = pack2(w.x, w.y);
            *(uint32_t*)(smem + A2HI + bo + 4) = pack2(w.z, w.w);
            *(uint32_t*)(smem + A2LO + bo)     = pack2(w.x - hx, w.y - hy);
            *(uint32_t*)(smem + A2LO + bo + 4) = pack2(w.z - hz, w.w - hw);
        }
        if (next < NT64) {
            const int nrow0 = next * 64;
#pragma unroll
            for (int it = 0; it < 8; it++) {
                int gr = nrow0 + lm + it * 8;
                v[it] = (gr < NN) ? *(const float4*)(X + gr * 128 + lc4)
                                  : make_float4(0.f, 0.f, 0.f, 0.f);
            }
        }
        __syncthreads();

        float c[2][4][4];
#pragma unroll
        for (int i = 0; i < 2; i++)
#pragma unroll
            for (int j = 0; j < 4; j++)
#pragma unroll
                for (int z = 0; z < 4; z++) c[i][j][z] = 0.f;

#pragma unroll 2
        for (int k0 = 0; k0 < 128; k0 += 16) {
            const uint32_t kB = (uint32_t)(k0 * 2);
#pragma unroll
            for (int term = 0; term < 3; term++) {
                const uint32_t aSel = (term == 2) ? aLoB : aHiB;
                const uint32_t bSel = (term == 1) ? bLoB : bHiB;
                uint32_t a[2][4];
#pragma unroll
                for (int mf = 0; mf < 2; mf++)
                    ldm4(a[mf], aSel + aOff + mf * (16 * TSTRIDE) + kB);
#pragma unroll
                for (int nf2 = 0; nf2 < 2; nf2++) {
                    uint32_t bb[4];
                    ldm4(bb, bSel + bOff + nf2 * (16 * TSTRIDE) + kB);
#pragma unroll
                    for (int mf = 0; mf < 2; mf++) {
                        mma16816(c[mf][nf2 * 2],     a[mf], bb[0], bb[1]);
                        mma16816(c[mf][nf2 * 2 + 1], a[mf], bb[2], bb[3]);
                    }
                }
            }
        }

        // ---- epilogue: R path -> fp32 f buffer; W path -> fp16 g_h ----
#pragma unroll
        for (int nf = 0; nf < 4; nf++) {
            const int col = n0 + nf * 8 + 2 * t4;
#pragma unroll
            for (int mf = 0; mf < 2; mf++) {
                int rlo = row0 + wm * 32 + mf * 16 + gq;
                if (isR) {
                    if (rlo < NN) {
                        float2 o = make_float2(c[mf][nf][0] + bx[nf], c[mf][nf][1] + by[nf]);
                        *(float2*)(dstF + rlo * 128 + col) = o;
                    }
                    if (rlo + 8 < NN) {
                        float2 o = make_float2(c[mf][nf][2] + bx[nf], c[mf][nf][3] + by[nf]);
                        *(float2*)(dstF + (rlo + 8) * 128 + col) = o;
                    }
                } else {
                    if (rlo < NN)
                        *(__half2*)(g_h + rlo * 128 + col) =
                            __floats2half2_rn(c[mf][nf][0], c[mf][nf][1]);
                    if (rlo + 8 < NN)
                        *(__half2*)(g_h + (rlo + 8) * 128 + col) =
                            __floats2half2_rn(c[mf][nf][2], c[mf][nf][3]);
                }
            }
        }
        tile = next;
    }
}

// ---------------- graph preprocessing --------------------------------------
__global__ void k_deg(const int* __restrict__ ei) {
    int e = blockIdx.x * blockDim.x + threadIdx.x;
    if (e < NE) {
        int d = ei[NE + e];
        if (d >= 0 && d < NN) atomicAdd(&g_deg[d], 1);
    }
}

__global__ void k_off() {
    __shared__ int sh[256];
    __shared__ int base;
    const int t = threadIdx.x;
    const int i = blockIdx.x * 256 + t;
    int d = (i < NN) ? g_deg[i] : 0;
    if (i < NN) g_dinv[i] = (d > 0) ? rsqrtf((float)d) : 0.f;
    sh[t] = d;
    __syncthreads();
    for (int off = 1; off < 256; off <<= 1) {
        int v = (t >= off) ? sh[t - off] : 0;
        __syncthreads();
        sh[t] += v;
        __syncthreads();
    }
    if (t == 255) base = atomicAdd(&g_total, sh[255]);
    __syncthreads();
    if (i < NN) g_beg[i] = base + sh[t] - d;
}

// fill atomics run directly on g_beg; afterwards g_beg[i] == segment END
__global__ void k_fill(const int* __restrict__ ei) {
    int e = blockIdx.x * blockDim.x + threadIdx.x;
    if (e < NE) {
        int s = ei[e];
        int d = ei[NE + e];
        if (s < 0 || s >= NN || d < 0 || d >= NN) return;
        float w = g_dinv[s] * g_dinv[d];
        int pos = atomicAdd(&g_beg[d], 1);
        g_src[pos] = s;
        g_w[pos] = w;
    }
}

// ---------------- CSR aggregation: warp per node, fp16 gather ---------------
// last!=0: apply relu and write to lastOut instead of f
__global__ void k_agg(int outSel, int last, float* __restrict__ lastOut) {
    float* f = selBuf(outSel);
    const int wid = threadIdx.x >> 5, lane = threadIdx.x & 31;
    const int i = blockIdx.x * 4 + wid;
    if (i >= NN) return;
    const int end = g_beg[i];              // g_beg holds END after k_fill
    const int beg = end - g_deg[i];
    const int laneOff = lane * 4;          // 4 fp16 cols per lane
    float4 acc = *(float4*)(f + i * HH + laneOff);
    int e = beg;
    for (; e + 4 <= end; e += 4) {
        int s0 = g_src[e], s1 = g_src[e+1], s2 = g_src[e+2], s3 = g_src[e+3];
        float w0 = g_w[e], w1 = g_w[e+1], w2 = g_w[e+2], w3 = g_w[e+3];
        uint2 u0 = *(const uint2*)(g_h + s0 * HH + laneOff);
        uint2 u1 = *(const uint2*)(g_h + s1 * HH + laneOff);
        uint2 u2 = *(const uint2*)(g_h + s2 * HH + laneOff);
        uint2 u3 = *(const uint2*)(g_h + s3 * HH + laneOff);
        float2 a0 = __half22float2(*(__half2*)&u0.x), b0 = __half22float2(*(__half2*)&u0.y);
        float2 a1 = __half22float2(*(__half2*)&u1.x), b1 = __half22float2(*(__half2*)&u1.y);
        float2 a2 = __half22float2(*(__half2*)&u2.x), b2 = __half22float2(*(__half2*)&u2.y);
        float2 a3 = __half22float2(*(__half2*)&u3.x), b3 = __half22float2(*(__half2*)&u3.y);
        acc.x += a0.x*w0 + a1.x*w1 + a2.x*w2 + a3.x*w3;
        acc.y += a0.y*w0 + a1.y*w1 + a2.y*w2 + a3.y*w3;
        acc.z += b0.x*w0 + b1.x*w1 + b2.x*w2 + b3.x*w3;
        acc.w += b0.y*w0 + b1.y*w1 + b2.y*w2 + b3.y*w3;
    }
    for (; e < end; e++) {
        int s = g_src[e];
        float w = g_w[e];
        uint2 u = *(const uint2*)(g_h + s * HH + laneOff);
        float2 a = __half22float2(*(__half2*)&u.x), b = __half22float2(*(__half2*)&u.y);
        acc.x += a.x * w; acc.y += a.y * w;
        acc.z += b.x * w; acc.w += b.y * w;
    }
    if (last) {
        acc.x = fmaxf(acc.x, 0.f); acc.y = fmaxf(acc.y, 0.f);
        acc.z = fmaxf(acc.z, 0.f); acc.w = fmaxf(acc.w, 0.f);
        *(float4*)(lastOut + i * HH + laneOff) = acc;
    } else {
        *(float4*)(f + i * HH + laneOff) = acc;
    }
}

// ---------------- mean-pool accumulation (input already relu'd) -------------
__global__ void k_pool(const float* __restrict__ f,
                       const int* __restrict__ batch) {
    const int t = threadIdx.x;
    const int base = blockIdx.x * 64;
    float acc = 0.f;
    int cur = -1;
    for (int r = 0; r < 64; r++) {
        int i = base + r;
        if (i >= NN) break;
        float v = f[i * HH + t];
        int bg = batch[i];
        if (bg != cur) {
            if (cur >= 0) atomicAdd(&g_pool[cur * HH + t], acc);
            cur = bg; acc = 0.f;
        }
        acc += v;
    }
    if (cur >= 0) atomicAdd(&g_pool[cur * HH + t], acc);
    if (t == 0) {
        int c = 0; int cb = -1;
        for (int r = 0; r < 64; r++) {
            int i = base + r;
            if (i >= NN) break;
            int bg = batch[i];
            if (bg != cb) {
                if (cb >= 0) atomicAdd(&g_cnt[cb], (float)c);
                cb = bg; c = 0;
            }
            c++;
        }
        if (cb >= 0) atomicAdd(&g_cnt[cb], (float)c);
    }
}

// ---------------- MLP head + log_softmax ------------------------------------
__global__ void k_head(const float* __restrict__ l1w, const float* __restrict__ l1b,
                       const float* __restrict__ l2w, const float* __restrict__ l2b,
                       float* __restrict__ out) {
    __shared__ float p[HH];
    __shared__ float gg[HH];
    __shared__ float lg[NC];
    const int g = blockIdx.x, t = threadIdx.x;
    float c = fmaxf(g_cnt[g], 1.f);
    p[t] = g_pool[g * HH + t] / c;
    __syncthreads();
    float a = l1b[t];
#pragma unroll 8
    for (int k = 0; k < HH; k++) a += p[k] * l1w[k * HH + t];
    gg[t] = fmaxf(a, 0.f);
    __syncthreads();
    if (t < NC) {
        float a2 = l2b[t];
        for (int k = 0; k < HH; k++) a2 += gg[k] * l2w[k * NC + t];
        lg[t] = a2;
    }
    __syncthreads();
    if (t < NC) {
        float m = lg[0];
        for (int j = 1; j < NC; j++) m = fmaxf(m, lg[j]);
        float s = 0.f;
        for (int j = 0; j < NC; j++) s += expf(lg[j] - m);
        out[g * NC + t] = lg[t] - m - logf(s);
    }
}

// ---------------- launch -----------------------------------------------------
extern "C" void kernel_launch(void* const* d_in, const int* in_sizes, int n_in,
                              void* d_out, int out_size) {
    const float* x     = (const float*)d_in[0];
    const int*   ei    = (const int*)d_in[1];
    const int*   batch = (const int*)d_in[2];
    const float* W1    = (const float*)d_in[3];
    const float* R1    = (const float*)d_in[4];
    const float* b1    = (const float*)d_in[5];
    const float* Wc    = (const float*)d_in[6];
    const float* Rc    = (const float*)d_in[7];
    const float* bc    = (const float*)d_in[8];
    const float* l1w   = (const float*)d_in[9];
    const float* l1b   = (const float*)d_in[10];
    const float* l2w   = (const float*)d_in[11];
    const float* l2b   = (const float*)d_in[12];
    float* out     = (float*)d_out;
    float* lastOut = out + NG * NC;   // tuple order: (log_softmax, last)

    cudaFuncSetAttribute(k_mmagemm, cudaFuncAttributeMaxDynamicSharedMemorySize, SM2_TOTAL);

    // preprocessing: zero+weight split fused, then CSR build
    k_pre <<<204, 256>>>(W1, R1, Wc, Rc);
    k_deg <<<(NE + 255) / 256, 256>>>(ei);
    k_off <<<(NN + 255) / 256, 256>>>();
    k_fill<<<(NE + 255) / 256, 256>>>(ei);

    // 4 GCS layers; last agg writes relu'd output straight into lastOut
    int inSel = -1;
    int outSel = 0;
    for (int l = 0; l < 4; l++) {
        const float* b = (l == 0) ? b1 : bc + (l - 1) * HH;
        k_mmagemm<<<dim3(GEMM_GRID, 2), 256, SM2_TOTAL>>>(x, inSel, outSel, l, b);
        k_agg<<<(NN + 3) / 4, 128>>>(outSel, (l == 3) ? 1 : 0, lastOut);
        inSel = outSel;
        outSel ^= 1;
    }

    k_pool<<<(NN + 63) / 64, 128>>>(lastOut, batch);
    k_head<<<NG, 128>>>(l1w, l1b, l2w, l2b, out);
}

// round 11
// speedup vs baseline: 4.8095x; 1.3770x over previous
#include <cuda_runtime.h>
#include <cuda_fp16.h>
#include <cstdint>

#define NN 50000
#define NE 600000
#define HH 128
#define NG 128
#define NC 10
#define NT64 782                    // ceil(50000/64)
#define GEMM_GRID 148

// ---------------- tile geometry ----------------------------------------------
#define TSTRIDE 272                 // 128 fp16 (256B) + 16B pad -> ldmatrix conflict-free
#define TILE_B  (128 * TSTRIDE)     // 34816 bytes per 128x128 fp16 image

// ---------------- scratch (static device globals; no allocation) ------------
__device__ __half g_h [NN*HH];     // W-path output, fp16
__device__ float g_f0[NN*HH];
__device__ float g_f1[NN*HH];
__device__ uint2 g_edge[NE];       // packed {src, bits(w)} CSR records
__device__ int   g_deg [NN];
__device__ int   g_beg [NN];       // after k_fill: END of each segment
__device__ int   g_total;
__device__ float g_dinv[NN];
__device__ float g_pool[NG*HH];
__device__ float g_cnt [NG];
// pre-converted fp16 weight images: [layer][W,R][TILE_B bytes]
__device__ __align__(16) char g_wimg[4][2][TILE_B];

__device__ __forceinline__ float* selBuf(int s) { return s ? g_f1 : g_f0; }

__device__ __forceinline__ uint32_t s2u(const void* p) {
    uint32_t a;
    asm("{ .reg .u64 t; cvta.to.shared.u64 t, %1; cvt.u32.u64 %0, t; }"
        : "=r"(a) : "l"(p));
    return a;
}

// ---------------- GEMM SMEM layout (per CTA: 52224 B -> 2 CTA/SM) -----------
#define A16  0
#define B16  17408                  // 64*272
#define SM2_TOTAL 52224

__device__ __forceinline__ void ldm4(uint32_t* r, uint32_t addr) {
    asm volatile("ldmatrix.sync.aligned.m8n8.x4.shared.b16 {%0,%1,%2,%3}, [%4];"
                 : "=r"(r[0]), "=r"(r[1]), "=r"(r[2]), "=r"(r[3]) : "r"(addr));
}
__device__ __forceinline__ void mma16816h(float* c, const uint32_t* a,
                                          uint32_t b0, uint32_t b1) {
    asm volatile(
        "mma.sync.aligned.m16n8k16.row.col.f32.f16.f16.f32 "
        "{%0,%1,%2,%3}, {%4,%5,%6,%7}, {%8,%9}, {%0,%1,%2,%3};"
        : "+f"(c[0]), "+f"(c[1]), "+f"(c[2]), "+f"(c[3])
        : "r"(a[0]), "r"(a[1]), "r"(a[2]), "r"(a[3]), "r"(b0), "r"(b1));
}

__device__ __forceinline__ uint32_t packh2(float a, float b) {
    __half2 h = __floats2half2_rn(a, b);
    return *(uint32_t*)&h;
}

// ---------------- fused: zero scratch + fp16 weight images ------------------
__global__ void k_pre(const float* __restrict__ W1, const float* __restrict__ R1,
                      const float* __restrict__ Wc, const float* __restrict__ Rc) {
    if (blockIdx.x < 196) {
        int i = blockIdx.x * 256 + threadIdx.x;
        if (i < NN) g_deg[i] = 0;
        if (i < NG*HH) g_pool[i] = 0.f;
        if (i < NG) g_cnt[i] = 0.f;
        if (i == 0) g_total = 0;
        return;
    }
    const int b = blockIdx.x - 196;
    const int layer = b >> 1;
    const int isR = b & 1;
    const float* src;
    if (layer == 0) src = isR ? R1 : W1;
    else src = (isR ? Rc : Wc) + (layer - 1) * HH * HH;
    char* img = g_wimg[layer][isR];
    for (int idx = threadIdx.x; idx < HH * HH; idx += 256) {
        int n = idx >> 7, k = idx & 127;
        __half h = __float2half(src[k * HH + n]);   // transpose [k][n] -> [n][k]
        *(unsigned short*)(img + n * TSTRIDE + k * 2) = *(unsigned short*)&h;
    }
}

// ---------------- persistent dual GEMM via fp16 mma.sync ---------------------
// blockIdx.y==0: out = relu?(X)@W -> g_h (fp16, no bias)
// blockIdx.y==1: out = relu?(X)@R + bias -> selBuf(outSel) (fp32)
__global__ void __launch_bounds__(256, 2) k_mmagemm(
    const float* __restrict__ Xext, int inSel, int outSel, int layer,
    const float* __restrict__ bias)
{
    extern __shared__ char smem[];
    const uint32_t sbase = s2u(smem);
    const int tid = threadIdx.x;
    const int wid = tid >> 5, lane = tid & 31;
    const int isR = blockIdx.y;
    const float* X = (inSel < 0) ? Xext : selBuf(inSel);
    const bool reluIn = (inSel >= 0);
    float* dstF = selBuf(outSel);

    // ---- B image (34816 B) loaded ONCE per persistent CTA ----
    {
        const float4* src = (const float4*)g_wimg[layer][isR];
        float4* d4 = (float4*)(smem + B16);
#pragma unroll
        for (int it = 0; it < 8; it++)
            d4[it * 256 + tid] = src[it * 256 + tid];
        if (tid < 128) d4[8 * 256 + tid] = src[8 * 256 + tid];   // 2176 total
    }

    // warp decomposition: warp grid 2(m) x 4(n), warp tile m32 x n32
    const int wm = wid & 1;
    const int wn = wid >> 1;
    const int n0 = wn * 32;
    const uint32_t aOff = (uint32_t)((wm * 32 + (lane & 15)) * TSTRIDE
                                     + (lane >> 4) * 16);
    const int q = lane >> 3, r8 = lane & 7;
    const uint32_t bOff = (uint32_t)((n0 + ((q & 2) << 2) + r8) * TSTRIDE
                                     + (q & 1) * 16);
    const uint32_t aB = sbase + A16, bB = sbase + B16;
    const int gq = lane >> 2, t4 = lane & 3;

    float bx[4], by[4];
#pragma unroll
    for (int nf = 0; nf < 4; nf++) {
        if (isR) {
            float2 bv = *(const float2*)(bias + n0 + nf * 8 + 2 * t4);
            bx[nf] = bv.x; by[nf] = bv.y;
        } else { bx[nf] = 0.f; by[nf] = 0.f; }
    }

    const int lm = tid >> 5;
    const int lc4 = (tid & 31) * 4;

    float4 v[8];
    int tile = blockIdx.x;
    {
        const int row0 = tile * 64;
#pragma unroll
        for (int it = 0; it < 8; it++) {
            int gr = row0 + lm + it * 8;
            v[it] = (gr < NN) ? *(const float4*)(X + gr * 128 + lc4)
                              : make_float4(0.f, 0.f, 0.f, 0.f);
        }
    }

    while (tile < NT64) {
        const int row0 = tile * 64;
        const int next = tile + GEMM_GRID;

        __syncthreads();
        // ---- convert prefetched regs -> SMEM fp16 ----
#pragma unroll
        for (int it = 0; it < 8; it++) {
            float4 w = v[it];
            if (reluIn) {
                w.x = fmaxf(w.x, 0.f); w.y = fmaxf(w.y, 0.f);
                w.z = fmaxf(w.z, 0.f); w.w = fmaxf(w.w, 0.f);
            }
            uint32_t bo = (lm + it * 8) * TSTRIDE + lc4 * 2;
            *(uint32_t*)(smem + A16 + bo)     = packh2(w.x, w.y);
            *(uint32_t*)(smem + A16 + bo + 4) = packh2(w.z, w.w);
        }
        if (next < NT64) {
            const int nrow0 = next * 64;
#pragma unroll
            for (int it = 0; it < 8; it++) {
                int gr = nrow0 + lm + it * 8;
                v[it] = (gr < NN) ? *(const float4*)(X + gr * 128 + lc4)
                                  : make_float4(0.f, 0.f, 0.f, 0.f);
            }
        }
        __syncthreads();

        float c[2][4][4];
#pragma unroll
        for (int i = 0; i < 2; i++)
#pragma unroll
            for (int j = 0; j < 4; j++)
#pragma unroll
                for (int z = 0; z < 4; z++) c[i][j][z] = 0.f;

#pragma unroll 2
        for (int k0 = 0; k0 < 128; k0 += 16) {
            const uint32_t kB = (uint32_t)(k0 * 2);
            uint32_t a[2][4];
#pragma unroll
            for (int mf = 0; mf < 2; mf++)
                ldm4(a[mf], aB + aOff + mf * (16 * TSTRIDE) + kB);
#pragma unroll
            for (int nf2 = 0; nf2 < 2; nf2++) {
                uint32_t bb[4];
                ldm4(bb, bB + bOff + nf2 * (16 * TSTRIDE) + kB);
#pragma unroll
                for (int mf = 0; mf < 2; mf++) {
                    mma16816h(c[mf][nf2 * 2],     a[mf], bb[0], bb[1]);
                    mma16816h(c[mf][nf2 * 2 + 1], a[mf], bb[2], bb[3]);
                }
            }
        }

        // ---- epilogue: R path -> fp32 f buffer; W path -> fp16 g_h ----
#pragma unroll
        for (int nf = 0; nf < 4; nf++) {
            const int col = n0 + nf * 8 + 2 * t4;
#pragma unroll
            for (int mf = 0; mf < 2; mf++) {
                int rlo = row0 + wm * 32 + mf * 16 + gq;
                if (isR) {
                    if (rlo < NN) {
                        float2 o = make_float2(c[mf][nf][0] + bx[nf], c[mf][nf][1] + by[nf]);
                        *(float2*)(dstF + rlo * 128 + col) = o;
                    }
                    if (rlo + 8 < NN) {
                        float2 o = make_float2(c[mf][nf][2] + bx[nf], c[mf][nf][3] + by[nf]);
                        *(float2*)(dstF + (rlo + 8) * 128 + col) = o;
                    }
                } else {
                    if (rlo < NN)
                        *(__half2*)(g_h + rlo * 128 + col) =
                            __floats2half2_rn(c[mf][nf][0], c[mf][nf][1]);
                    if (rlo + 8 < NN)
                        *(__half2*)(g_h + (rlo + 8) * 128 + col) =
                            __floats2half2_rn(c[mf][nf][2], c[mf][nf][3]);
                }
            }
        }
        tile = next;
    }
}

// ---------------- graph preprocessing --------------------------------------
__global__ void k_deg(const int* __restrict__ ei) {
    int e = blockIdx.x * blockDim.x + threadIdx.x;
    if (e < NE) {
        int d = ei[NE + e];
        if (d >= 0 && d < NN) atomicAdd(&g_deg[d], 1);
    }
}

__global__ void k_off() {
    __shared__ int sh[256];
    __shared__ int base;
    const int t = threadIdx.x;
    const int i = blockIdx.x * 256 + t;
    int d = (i < NN) ? g_deg[i] : 0;
    if (i < NN) g_dinv[i] = (d > 0) ? rsqrtf((float)d) : 0.f;
    sh[t] = d;
    __syncthreads();
    for (int off = 1; off < 256; off <<= 1) {
        int v = (t >= off) ? sh[t - off] : 0;
        __syncthreads();
        sh[t] += v;
        __syncthreads();
    }
    if (t == 255) base = atomicAdd(&g_total, sh[255]);
    __syncthreads();
    if (i < NN) g_beg[i] = base + sh[t] - d;
}

// fill atomics run directly on g_beg; afterwards g_beg[i] == segment END
__global__ void k_fill(const int* __restrict__ ei) {
    int e = blockIdx.x * blockDim.x + threadIdx.x;
    if (e < NE) {
        int s = ei[e];
        int d = ei[NE + e];
        if (s < 0 || s >= NN || d < 0 || d >= NN) return;
        float w = g_dinv[s] * g_dinv[d];
        int pos = atomicAdd(&g_beg[d], 1);
        g_edge[pos] = make_uint2((uint32_t)s, __float_as_uint(w));
    }
}

// ---------------- CSR aggregation: warp per node, fp16 gather ---------------
// last!=0: apply relu and write to lastOut instead of f
__global__ void k_agg(int outSel, int last, float* __restrict__ lastOut) {
    float* f = selBuf(outSel);
    const int wid = threadIdx.x >> 5, lane = threadIdx.x & 31;
    const int i = blockIdx.x * 4 + wid;
    if (i >= NN) return;
    const int end = g_beg[i];              // g_beg holds END after k_fill
    const int beg = end - g_deg[i];
    const int laneOff = lane * 4;          // 4 fp16 cols per lane
    float4 acc = *(float4*)(f + i * HH + laneOff);
    int e = beg;
    for (; e + 4 <= end; e += 4) {
        uint2 e0 = g_edge[e],   e1 = g_edge[e+1];
        uint2 e2 = g_edge[e+2], e3 = g_edge[e+3];
        float w0 = __uint_as_float(e0.y), w1 = __uint_as_float(e1.y);
        float w2 = __uint_as_float(e2.y), w3 = __uint_as_float(e3.y);
        uint2 u0 = *(const uint2*)(g_h + e0.x * HH + laneOff);
        uint2 u1 = *(const uint2*)(g_h + e1.x * HH + laneOff);
        uint2 u2 = *(const uint2*)(g_h + e2.x * HH + laneOff);
        uint2 u3 = *(const uint2*)(g_h + e3.x * HH + laneOff);
        float2 a0 = __half22float2(*(__half2*)&u0.x), b0 = __half22float2(*(__half2*)&u0.y);
        float2 a1 = __half22float2(*(__half2*)&u1.x), b1 = __half22float2(*(__half2*)&u1.y);
        float2 a2 = __half22float2(*(__half2*)&u2.x), b2 = __half22float2(*(__half2*)&u2.y);
        float2 a3 = __half22float2(*(__half2*)&u3.x), b3 = __half22float2(*(__half2*)&u3.y);
        acc.x += a0.x*w0 + a1.x*w1 + a2.x*w2 + a3.x*w3;
        acc.y += a0.y*w0 + a1.y*w1 + a2.y*w2 + a3.y*w3;
        acc.z += b0.x*w0 + b1.x*w1 + b2.x*w2 + b3.x*w3;
        acc.w += b0.y*w0 + b1.y*w1 + b2.y*w2 + b3.y*w3;
    }
    for (; e < end; e++) {
        uint2 ed = g_edge[e];
        float w = __uint_as_float(ed.y);
        uint2 u = *(const uint2*)(g_h + ed.x * HH + laneOff);
        float2 a = __half22float2(*(__half2*)&u.x), b = __half22float2(*(__half2*)&u.y);
        acc.x += a.x * w; acc.y += a.y * w;
        acc.z += b.x * w; acc.w += b.y * w;
    }
    if (last) {
        acc.x = fmaxf(acc.x, 0.f); acc.y = fmaxf(acc.y, 0.f);
        acc.z = fmaxf(acc.z, 0.f); acc.w = fmaxf(acc.w, 0.f);
        *(float4*)(lastOut + i * HH + laneOff) = acc;
    } else {
        *(float4*)(f + i * HH + laneOff) = acc;
    }
}

// ---------------- mean-pool accumulation (input already relu'd) -------------
__global__ void k_pool(const float* __restrict__ f,
                       const int* __restrict__ batch) {
    const int t = threadIdx.x;
    const int base = blockIdx.x * 64;
    float acc = 0.f;
    int cur = -1;
    for (int r = 0; r < 64; r++) {
        int i = base + r;
        if (i >= NN) break;
        float v = f[i * HH + t];
        int bg = batch[i];
        if (bg != cur) {
            if (cur >= 0) atomicAdd(&g_pool[cur * HH + t], acc);
            cur = bg; acc = 0.f;
        }
        acc += v;
    }
    if (cur >= 0) atomicAdd(&g_pool[cur * HH + t], acc);
    if (t == 0) {
        int c = 0; int cb = -1;
        for (int r = 0; r < 64; r++) {
            int i = base + r;
            if (i >= NN) break;
            int bg = batch[i];
            if (bg != cb) {
                if (cb >= 0) atomicAdd(&g_cnt[cb], (float)c);
                cb = bg; c = 0;
            }
            c++;
        }
        if (cb >= 0) atomicAdd(&g_cnt[cb], (float)c);
    }
}

// ---------------- MLP head + log_softmax ------------------------------------
__global__ void k_head(const float* __restrict__ l1w, const float* __restrict__ l1b,
                       const float* __restrict__ l2w, const float* __restrict__ l2b,
                       float* __restrict__ out) {
    __shared__ float p[HH];
    __shared__ float gg[HH];
    __shared__ float lg[NC];
    const int g = blockIdx.x, t = threadIdx.x;
    float c = fmaxf(g_cnt[g], 1.f);
    p[t] = g_pool[g * HH + t] / c;
    __syncthreads();
    float a = l1b[t];
#pragma unroll 8
    for (int k = 0; k < HH; k++) a += p[k] * l1w[k * HH + t];
    gg[t] = fmaxf(a, 0.f);
    __syncthreads();
    if (t < NC) {
        float a2 = l2b[t];
        for (int k = 0; k < HH; k++) a2 += gg[k] * l2w[k * NC + t];
        lg[t] = a2;
    }
    __syncthreads();
    if (t < NC) {
        float m = lg[0];
        for (int j = 1; j < NC; j++) m = fmaxf(m, lg[j]);
        float s = 0.f;
        for (int j = 0; j < NC; j++) s += expf(lg[j] - m);
        out[g * NC + t] = lg[t] - m - logf(s);
    }
}

// ---------------- launch -----------------------------------------------------
extern "C" void kernel_launch(void* const* d_in, const int* in_sizes, int n_in,
                              void* d_out, int out_size) {
    const float* x     = (const float*)d_in[0];
    const int*   ei    = (const int*)d_in[1];
    const int*   batch = (const int*)d_in[2];
    const float* W1    = (const float*)d_in[3];
    const float* R1    = (const float*)d_in[4];
    const float* b1    = (const float*)d_in[5];
    const float* Wc    = (const float*)d_in[6];
    const float* Rc    = (const float*)d_in[7];
    const float* bc    = (const float*)d_in[8];
    const float* l1w   = (const float*)d_in[9];
    const float* l1b   = (const float*)d_in[10];
    const float* l2w   = (const float*)d_in[11];
    const float* l2b   = (const float*)d_in[12];
    float* out     = (float*)d_out;
    float* lastOut = out + NG * NC;   // tuple order: (log_softmax, last)

    cudaFuncSetAttribute(k_mmagemm, cudaFuncAttributeMaxDynamicSharedMemorySize, SM2_TOTAL);

    // preprocessing: zero+weight convert fused, then CSR build
    k_pre <<<204, 256>>>(W1, R1, Wc, Rc);
    k_deg <<<(NE + 255) / 256, 256>>>(ei);
    k_off <<<(NN + 255) / 256, 256>>>();
    k_fill<<<(NE + 255) / 256, 256>>>(ei);

    // 4 GCS layers; last agg writes relu'd output straight into lastOut
    int inSel = -1;
    int outSel = 0;
    for (int l = 0; l < 4; l++) {
        const float* b = (l == 0) ? b1 : bc + (l - 1) * HH;
        k_mmagemm<<<dim3(GEMM_GRID, 2), 256, SM2_TOTAL>>>(x, inSel, outSel, l, b);
        k_agg<<<(NN + 3) / 4, 128>>>(outSel, (l == 3) ? 1 : 0, lastOut);
        inSel = outSel;
        outSel ^= 1;
    }

    k_pool<<<(NN + 63) / 64, 128>>>(lastOut, batch);
    k_head<<<NG, 128>>>(l1w, l1b, l2w, l2b, out);
}

// round 12
// speedup vs baseline: 4.9082x; 1.0205x over previous
#include <cuda_runtime.h>
#include <cuda_fp16.h>
#include <cstdint>

#define NN 50000
#define NE 600000
#define HH 128
#define NG 128
#define NC 10
#define NT64 782                    // ceil(50000/64)
#define GEMM_GRID 296               // 2 CTAs per SM, persistent

// ---------------- tile geometry ----------------------------------------------
#define TSTRIDE 272                 // 128 fp16 (256B) + 16B pad -> ldmatrix conflict-free
#define TILE_B  (128 * TSTRIDE)     // 34816 bytes per 128x128 fp16 image

// ---------------- scratch (static device globals; no allocation) ------------
__device__ __half g_h [NN*HH];     // W-path output, fp16
__device__ float g_f0[NN*HH];
__device__ float g_f1[NN*HH];
__device__ uint2 g_edge[NE];       // packed {src, bits(w)} CSR records
__device__ int   g_deg [NN];
__device__ int   g_beg [NN];       // after k_fill: END of each segment
__device__ int   g_total;
__device__ float g_dinv[NN];
__device__ float g_pool[NG*HH];
__device__ float g_cnt [NG];
// fp16 weight images: [layer][W,R][TILE_B] -- W,R contiguous per layer
__device__ __align__(16) char g_wimg[4][2][TILE_B];

__device__ __forceinline__ float* selBuf(int s) { return s ? g_f1 : g_f0; }

__device__ __forceinline__ uint32_t s2u(const void* p) {
    uint32_t a;
    asm("{ .reg .u64 t; cvta.to.shared.u64 t, %1; cvt.u32.u64 %0, t; }"
        : "=r"(a) : "l"(p));
    return a;
}

// ---------------- GEMM SMEM layout (per CTA: 87040 B -> 2 CTA/SM) -----------
#define A16  0
#define BW16 17408                  // W image
#define BR16 (17408 + TILE_B)       // R image
#define SM2_TOTAL (17408 + 2 * TILE_B)   // 87040

__device__ __forceinline__ void ldm4(uint32_t* r, uint32_t addr) {
    asm volatile("ldmatrix.sync.aligned.m8n8.x4.shared.b16 {%0,%1,%2,%3}, [%4];"
                 : "=r"(r[0]), "=r"(r[1]), "=r"(r[2]), "=r"(r[3]) : "r"(addr));
}
__device__ __forceinline__ void mma16816h(float* c, const uint32_t* a,
                                          uint32_t b0, uint32_t b1) {
    asm volatile(
        "mma.sync.aligned.m16n8k16.row.col.f32.f16.f16.f32 "
        "{%0,%1,%2,%3}, {%4,%5,%6,%7}, {%8,%9}, {%0,%1,%2,%3};"
        : "+f"(c[0]), "+f"(c[1]), "+f"(c[2]), "+f"(c[3])
        : "r"(a[0]), "r"(a[1]), "r"(a[2]), "r"(a[3]), "r"(b0), "r"(b1));
}

__device__ __forceinline__ uint32_t packh2(float a, float b) {
    __half2 h = __floats2half2_rn(a, b);
    return *(uint32_t*)&h;
}

// ---------------- fused: zero scratch + fp16 weight images ------------------
__global__ void k_pre(const float* __restrict__ W1, const float* __restrict__ R1,
                      const float* __restrict__ Wc, const float* __restrict__ Rc) {
    if (blockIdx.x < 196) {
        int i = blockIdx.x * 256 + threadIdx.x;
        if (i < NN) g_deg[i] = 0;
        if (i < NG*HH) g_pool[i] = 0.f;
        if (i < NG) g_cnt[i] = 0.f;
        if (i == 0) g_total = 0;
        return;
    }
    const int b = blockIdx.x - 196;
    const int layer = b >> 1;
    const int isR = b & 1;
    const float* src;
    if (layer == 0) src = isR ? R1 : W1;
    else src = (isR ? Rc : Wc) + (layer - 1) * HH * HH;
    char* img = g_wimg[layer][isR];
    for (int idx = threadIdx.x; idx < HH * HH; idx += 256) {
        int n = idx >> 7, k = idx & 127;
        __half h = __float2half(src[k * HH + n]);   // transpose [k][n] -> [n][k]
        *(unsigned short*)(img + n * TSTRIDE + k * 2) = *(unsigned short*)&h;
    }
}

// ---------------- persistent fused dual-output GEMM --------------------------
// one CTA per tile computes BOTH: g_h = relu?(X)@W (fp16) and
//                                  f  = relu?(X)@R + bias (fp32)
// 256 threads, 8 warps: warp grid 2(m) x 4(n), warp tile m32 x n32 x {W,R}
__global__ void __launch_bounds__(256, 2) k_mmagemm(
    const float* __restrict__ Xext, int inSel, int outSel, int layer,
    const float* __restrict__ bias)
{
    extern __shared__ char smem[];
    const uint32_t sbase = s2u(smem);
    const int tid = threadIdx.x;
    const int wid = tid >> 5, lane = tid & 31;
    const float* X = (inSel < 0) ? Xext : selBuf(inSel);
    const bool reluIn = (inSel >= 0);
    float* dstF = selBuf(outSel);

    // ---- both B images (69632 B contiguous) loaded ONCE per CTA ----
    {
        const float4* src = (const float4*)g_wimg[layer][0];
        float4* d4 = (float4*)(smem + BW16);
#pragma unroll
        for (int it = 0; it < 17; it++)
            d4[it * 256 + tid] = src[it * 256 + tid];
    }

    // warp decomposition
    const int wm = wid & 1;
    const int wn = wid >> 1;           // 0..3
    const int n0 = wn * 32;
    const uint32_t aOff = (uint32_t)((wm * 32 + (lane & 15)) * TSTRIDE
                                     + (lane >> 4) * 16);
    const int q = lane >> 3, r8 = lane & 7;
    const uint32_t bOff = (uint32_t)((n0 + ((q & 2) << 2) + r8) * TSTRIDE
                                     + (q & 1) * 16);
    const uint32_t aB = sbase + A16;
    const uint32_t bWB = sbase + BW16, bRB = sbase + BR16;
    const int gq = lane >> 2, t4 = lane & 3;

    float bx[4], by[4];
#pragma unroll
    for (int nf = 0; nf < 4; nf++) {
        float2 bv = *(const float2*)(bias + n0 + nf * 8 + 2 * t4);
        bx[nf] = bv.x; by[nf] = bv.y;
    }

    const int lm = tid >> 5;           // A-load base row
    const int lc4 = (tid & 31) * 4;    // A-load col

    for (int tile = blockIdx.x; tile < NT64; tile += GEMM_GRID) {
        const int row0 = tile * 64;

        __syncthreads();   // previous mainloop done reading A
        // ---- A tile: 64x128 fp32 -> fp16, 8 float4 per thread ----
#pragma unroll
        for (int it = 0; it < 8; it++) {
            int gr = row0 + lm + it * 8;
            float4 w = (gr < NN) ? *(const float4*)(X + gr * 128 + lc4)
                                 : make_float4(0.f, 0.f, 0.f, 0.f);
            if (reluIn) {
                w.x = fmaxf(w.x, 0.f); w.y = fmaxf(w.y, 0.f);
                w.z = fmaxf(w.z, 0.f); w.w = fmaxf(w.w, 0.f);
            }
            uint32_t bo = (lm + it * 8) * TSTRIDE + lc4 * 2;
            *(uint32_t*)(smem + A16 + bo)     = packh2(w.x, w.y);
            *(uint32_t*)(smem + A16 + bo + 4) = packh2(w.z, w.w);
        }
        __syncthreads();

        float cW[2][4][4], cR[2][4][4];
#pragma unroll
        for (int i = 0; i < 2; i++)
#pragma unroll
            for (int j = 0; j < 4; j++)
#pragma unroll
                for (int z = 0; z < 4; z++) { cW[i][j][z] = 0.f; cR[i][j][z] = 0.f; }

#pragma unroll 1
        for (int k0 = 0; k0 < 128; k0 += 16) {
            const uint32_t kB = (uint32_t)(k0 * 2);
            uint32_t a[2][4];
#pragma unroll
            for (int mf = 0; mf < 2; mf++)
                ldm4(a[mf], aB + aOff + mf * (16 * TSTRIDE) + kB);
#pragma unroll
            for (int nf2 = 0; nf2 < 2; nf2++) {
                uint32_t bb[4];
                ldm4(bb, bWB + bOff + nf2 * (16 * TSTRIDE) + kB);
#pragma unroll
                for (int mf = 0; mf < 2; mf++) {
                    mma16816h(cW[mf][nf2 * 2],     a[mf], bb[0], bb[1]);
                    mma16816h(cW[mf][nf2 * 2 + 1], a[mf], bb[2], bb[3]);
                }
                ldm4(bb, bRB + bOff + nf2 * (16 * TSTRIDE) + kB);
#pragma unroll
                for (int mf = 0; mf < 2; mf++) {
                    mma16816h(cR[mf][nf2 * 2],     a[mf], bb[0], bb[1]);
                    mma16816h(cR[mf][nf2 * 2 + 1], a[mf], bb[2], bb[3]);
                }
            }
        }

        // ---- epilogue: W -> fp16 g_h ; R + bias -> fp32 f ----
#pragma unroll
        for (int nf = 0; nf < 4; nf++) {
            const int col = n0 + nf * 8 + 2 * t4;
#pragma unroll
            for (int mf = 0; mf < 2; mf++) {
                int rlo = row0 + wm * 32 + mf * 16 + gq;
                if (rlo < NN) {
                    *(__half2*)(g_h + rlo * 128 + col) =
                        __floats2half2_rn(cW[mf][nf][0], cW[mf][nf][1]);
                    *(float2*)(dstF + rlo * 128 + col) =
                        make_float2(cR[mf][nf][0] + bx[nf], cR[mf][nf][1] + by[nf]);
                }
                if (rlo + 8 < NN) {
                    *(__half2*)(g_h + (rlo + 8) * 128 + col) =
                        __floats2half2_rn(cW[mf][nf][2], cW[mf][nf][3]);
                    *(float2*)(dstF + (rlo + 8) * 128 + col) =
                        make_float2(cR[mf][nf][2] + bx[nf], cR[mf][nf][3] + by[nf]);
                }
            }
        }
    }
}

// ---------------- graph preprocessing --------------------------------------
__global__ void k_deg(const int* __restrict__ ei) {
    int e = blockIdx.x * blockDim.x + threadIdx.x;
    if (e < NE) {
        int d = ei[NE + e];
        if (d >= 0 && d < NN) atomicAdd(&g_deg[d], 1);
    }
}

__global__ void k_off() {
    __shared__ int sh[256];
    __shared__ int base;
    const int t = threadIdx.x;
    const int i = blockIdx.x * 256 + t;
    int d = (i < NN) ? g_deg[i] : 0;
    if (i < NN) g_dinv[i] = (d > 0) ? rsqrtf((float)d) : 0.f;
    sh[t] = d;
    __syncthreads();
    for (int off = 1; off < 256; off <<= 1) {
        int v = (t >= off) ? sh[t - off] : 0;
        __syncthreads();
        sh[t] += v;
        __syncthreads();
    }
    if (t == 255) base = atomicAdd(&g_total, sh[255]);
    __syncthreads();
    if (i < NN) g_beg[i] = base + sh[t] - d;
}

// fill atomics run directly on g_beg; afterwards g_beg[i] == segment END
__global__ void k_fill(const int* __restrict__ ei) {
    int e = blockIdx.x * blockDim.x + threadIdx.x;
    if (e < NE) {
        int s = ei[e];
        int d = ei[NE + e];
        if (s < 0 || s >= NN || d < 0 || d >= NN) return;
        float w = g_dinv[s] * g_dinv[d];
        int pos = atomicAdd(&g_beg[d], 1);
        g_edge[pos] = make_uint2((uint32_t)s, __float_as_uint(w));
    }
}

// ---------------- CSR aggregation: warp per node, fp16 gather ---------------
__global__ void k_agg(int outSel, int last, float* __restrict__ lastOut) {
    float* f = selBuf(outSel);
    const int wid = threadIdx.x >> 5, lane = threadIdx.x & 31;
    const int i = blockIdx.x * 4 + wid;
    if (i >= NN) return;
    const int end = g_beg[i];
    const int beg = end - g_deg[i];
    const int laneOff = lane * 4;
    float4 acc = *(float4*)(f + i * HH + laneOff);
    int e = beg;
    for (; e + 4 <= end; e += 4) {
        uint2 e0 = g_edge[e],   e1 = g_edge[e+1];
        uint2 e2 = g_edge[e+2], e3 = g_edge[e+3];
        float w0 = __uint_as_float(e0.y), w1 = __uint_as_float(e1.y);
        float w2 = __uint_as_float(e2.y), w3 = __uint_as_float(e3.y);
        uint2 u0 = *(const uint2*)(g_h + e0.x * HH + laneOff);
        uint2 u1 = *(const uint2*)(g_h + e1.x * HH + laneOff);
        uint2 u2 = *(const uint2*)(g_h + e2.x * HH + laneOff);
        uint2 u3 = *(const uint2*)(g_h + e3.x * HH + laneOff);
        float2 a0 = __half22float2(*(__half2*)&u0.x), b0 = __half22float2(*(__half2*)&u0.y);
        float2 a1 = __half22float2(*(__half2*)&u1.x), b1 = __half22float2(*(__half2*)&u1.y);
        float2 a2 = __half22float2(*(__half2*)&u2.x), b2 = __half22float2(*(__half2*)&u2.y);
        float2 a3 = __half22float2(*(__half2*)&u3.x), b3 = __half22float2(*(__half2*)&u3.y);
        acc.x += a0.x*w0 + a1.x*w1 + a2.x*w2 + a3.x*w3;
        acc.y += a0.y*w0 + a1.y*w1 + a2.y*w2 + a3.y*w3;
        acc.z += b0.x*w0 + b1.x*w1 + b2.x*w2 + b3.x*w3;
        acc.w += b0.y*w0 + b1.y*w1 + b2.y*w2 + b3.y*w3;
    }
    for (; e < end; e++) {
        uint2 ed = g_edge[e];
        float w = __uint_as_float(ed.y);
        uint2 u = *(const uint2*)(g_h + ed.x * HH + laneOff);
        float2 a = __half22float2(*(__half2*)&u.x), b = __half22float2(*(__half2*)&u.y);
        acc.x += a.x * w; acc.y += a.y * w;
        acc.z += b.x * w; acc.w += b.y * w;
    }
    if (last) {
        acc.x = fmaxf(acc.x, 0.f); acc.y = fmaxf(acc.y, 0.f);
        acc.z = fmaxf(acc.z, 0.f); acc.w = fmaxf(acc.w, 0.f);
        *(float4*)(lastOut + i * HH + laneOff) = acc;
    } else {
        *(float4*)(f + i * HH + laneOff) = acc;
    }
}

// ---------------- mean-pool accumulation (input already relu'd) -------------
__global__ void k_pool(const float* __restrict__ f,
                       const int* __restrict__ batch) {
    const int t = threadIdx.x;
    const int base = blockIdx.x * 64;
    float acc = 0.f;
    int cur = -1;
    for (int r = 0; r < 64; r++) {
        int i = base + r;
        if (i >= NN) break;
        float v = f[i * HH + t];
        int bg = batch[i];
        if (bg != cur) {
            if (cur >= 0) atomicAdd(&g_pool[cur * HH + t], acc);
            cur = bg; acc = 0.f;
        }
        acc += v;
    }
    if (cur >= 0) atomicAdd(&g_pool[cur * HH + t], acc);
    if (t == 0) {
        int c = 0; int cb = -1;
        for (int r = 0; r < 64; r++) {
            int i = base + r;
            if (i >= NN) break;
            int bg = batch[i];
            if (bg != cb) {
                if (cb >= 0) atomicAdd(&g_cnt[cb], (float)c);
                cb = bg; c = 0;
            }
            c++;
        }
        if (cb >= 0) atomicAdd(&g_cnt[cb], (float)c);
    }
}

// ---------------- MLP head + log_softmax ------------------------------------
__global__ void k_head(const float* __restrict__ l1w, const float* __restrict__ l1b,
                       const float* __restrict__ l2w, const float* __restrict__ l2b,
                       float* __restrict__ out) {
    __shared__ float p[HH];
    __shared__ float gg[HH];
    __shared__ float lg[NC];
    const int g = blockIdx.x, t = threadIdx.x;
    float c = fmaxf(g_cnt[g], 1.f);
    p[t] = g_pool[g * HH + t] / c;
    __syncthreads();
    float a = l1b[t];
#pragma unroll 8
    for (int k = 0; k < HH; k++) a += p[k] * l1w[k * HH + t];
    gg[t] = fmaxf(a, 0.f);
    __syncthreads();
    if (t < NC) {
        float a2 = l2b[t];
        for (int k = 0; k < HH; k++) a2 += gg[k] * l2w[k * NC + t];
        lg[t] = a2;
    }
    __syncthreads();
    if (t < NC) {
        float m = lg[0];
        for (int j = 1; j < NC; j++) m = fmaxf(m, lg[j]);
        float s = 0.f;
        for (int j = 0; j < NC; j++) s += expf(lg[j] - m);
        out[g * NC + t] = lg[t] - m - logf(s);
    }
}

// ---------------- launch -----------------------------------------------------
extern "C" void kernel_launch(void* const* d_in, const int* in_sizes, int n_in,
                              void* d_out, int out_size) {
    const float* x     = (const float*)d_in[0];
    const int*   ei    = (const int*)d_in[1];
    const int*   batch = (const int*)d_in[2];
    const float* W1    = (const float*)d_in[3];
    const float* R1    = (const float*)d_in[4];
    const float* b1    = (const float*)d_in[5];
    const float* Wc    = (const float*)d_in[6];
    const float* Rc    = (const float*)d_in[7];
    const float* bc    = (const float*)d_in[8];
    const float* l1w   = (const float*)d_in[9];
    const float* l1b   = (const float*)d_in[10];
    const float* l2w   = (const float*)d_in[11];
    const float* l2b   = (const float*)d_in[12];
    float* out     = (float*)d_out;
    float* lastOut = out + NG * NC;   // tuple order: (log_softmax, last)

    cudaFuncSetAttribute(k_mmagemm, cudaFuncAttributeMaxDynamicSharedMemorySize, SM2_TOTAL);

    // preprocessing: zero+weight convert fused, then CSR build
    k_pre <<<204, 256>>>(W1, R1, Wc, Rc);
    k_deg <<<(NE + 255) / 256, 256>>>(ei);
    k_off <<<(NN + 255) / 256, 256>>>();
    k_fill<<<(NE + 255) / 256, 256>>>(ei);

    // 4 GCS layers; last agg writes relu'd output straight into lastOut
    int inSel = -1;
    int outSel = 0;
    for (int l = 0; l < 4; l++) {
        const float* b = (l == 0) ? b1 : bc + (l - 1) * HH;
        k_mmagemm<<<GEMM_GRID, 256, SM2_TOTAL>>>(x, inSel, outSel, l, b);
        k_agg<<<(NN + 3) / 4, 128>>>(outSel, (l == 3) ? 1 : 0, lastOut);
        inSel = outSel;
        outSel ^= 1;
    }

    k_pool<<<(NN + 63) / 64, 128>>>(lastOut, batch);
    k_head<<<NG, 128>>>(l1w, l1b, l2w, l2b, out);
}

// round 13
// speedup vs baseline: 5.1156x; 1.0423x over previous
#include <cuda_runtime.h>
#include <cuda_fp16.h>
#include <cstdint>

#define NN 50000
#define NE 600000
#define HH 128
#define NG 128
#define NC 10
#define NT64 782                    // ceil(50000/64)
#define GEMM_GRID 296               // 2 CTAs per SM, persistent

// ---------------- tile geometry ----------------------------------------------
#define TSTRIDE 272                 // 128 fp16 (256B) + 16B pad -> ldmatrix conflict-free
#define TILE_B  (128 * TSTRIDE)     // 34816 bytes per 128x128 fp16 image

// ---------------- scratch (static device globals; no allocation) ------------
__device__ __half g_h [NN*HH];     // W-path output, fp16
__device__ __half g_f0[NN*HH];     // activation ping (fp16, relu'd by agg)
__device__ __half g_f1[NN*HH];     // activation pong
__device__ uint2 g_edge[NE];       // packed {src, bits(w)} CSR records
__device__ int   g_deg [NN];
__device__ int   g_beg [NN];       // after k_fill: END of each segment
__device__ int   g_total;
__device__ float g_dinv[NN];
__device__ float g_pool[NG*HH];
__device__ float g_cnt [NG];
// fp16 weight images: [layer][W,R][TILE_B] -- W,R contiguous per layer
__device__ __align__(16) char g_wimg[4][2][TILE_B];

__device__ __forceinline__ __half* selBuf(int s) { return s ? g_f1 : g_f0; }

__device__ __forceinline__ uint32_t s2u(const void* p) {
    uint32_t a;
    asm("{ .reg .u64 t; cvta.to.shared.u64 t, %1; cvt.u32.u64 %0, t; }"
        : "=r"(a) : "l"(p));
    return a;
}

// ---------------- GEMM SMEM layout (per CTA: 87040 B -> 2 CTA/SM) -----------
#define A16  0
#define BW16 17408                  // W image
#define BR16 (17408 + TILE_B)       // R image
#define SM2_TOTAL (17408 + 2 * TILE_B)   // 87040

__device__ __forceinline__ void ldm4(uint32_t* r, uint32_t addr) {
    asm volatile("ldmatrix.sync.aligned.m8n8.x4.shared.b16 {%0,%1,%2,%3}, [%4];"
                 : "=r"(r[0]), "=r"(r[1]), "=r"(r[2]), "=r"(r[3]) : "r"(addr));
}
__device__ __forceinline__ void mma16816h(float* c, const uint32_t* a,
                                          uint32_t b0, uint32_t b1) {
    asm volatile(
        "mma.sync.aligned.m16n8k16.row.col.f32.f16.f16.f32 "
        "{%0,%1,%2,%3}, {%4,%5,%6,%7}, {%8,%9}, {%0,%1,%2,%3};"
        : "+f"(c[0]), "+f"(c[1]), "+f"(c[2]), "+f"(c[3])
        : "r"(a[0]), "r"(a[1]), "r"(a[2]), "r"(a[3]), "r"(b0), "r"(b1));
}

__device__ __forceinline__ uint32_t packh2(float a, float b) {
    __half2 h = __floats2half2_rn(a, b);
    return *(uint32_t*)&h;
}

// ---------------- fused: zero scratch + fp16 weight images ------------------
__global__ void k_pre(const float* __restrict__ W1, const float* __restrict__ R1,
                      const float* __restrict__ Wc, const float* __restrict__ Rc) {
    if (blockIdx.x < 196) {
        int i = blockIdx.x * 256 + threadIdx.x;
        if (i < NN) g_deg[i] = 0;
        if (i < NG*HH) g_pool[i] = 0.f;
        if (i < NG) g_cnt[i] = 0.f;
        if (i == 0) g_total = 0;
        return;
    }
    const int b = blockIdx.x - 196;
    const int layer = b >> 1;
    const int isR = b & 1;
    const float* src;
    if (layer == 0) src = isR ? R1 : W1;
    else src = (isR ? Rc : Wc) + (layer - 1) * HH * HH;
    char* img = g_wimg[layer][isR];
    for (int idx = threadIdx.x; idx < HH * HH; idx += 256) {
        int n = idx >> 7, k = idx & 127;
        __half h = __float2half(src[k * HH + n]);   // transpose [k][n] -> [n][k]
        *(unsigned short*)(img + n * TSTRIDE + k * 2) = *(unsigned short*)&h;
    }
}

// ---------------- persistent fused dual-output GEMM --------------------------
// one CTA per tile computes BOTH: g_h = X@W (fp16) and f16 = X@R + bias (fp16)
// X: layer 0 = external fp32 x (no relu); layers 1-3 = fp16 buffer (already relu'd)
__global__ void __launch_bounds__(256, 2) k_mmagemm(
    const float* __restrict__ Xext, int inSel, int outSel, int layer,
    const float* __restrict__ bias)
{
    extern __shared__ char smem[];
    const uint32_t sbase = s2u(smem);
    const int tid = threadIdx.x;
    const int wid = tid >> 5, lane = tid & 31;
    const __half* X16 = (inSel < 0) ? (const __half*)0 : selBuf(inSel);
    __half* dstF = selBuf(outSel);

    // ---- both B images (69632 B contiguous) loaded ONCE per CTA ----
    {
        const float4* src = (const float4*)g_wimg[layer][0];
        float4* d4 = (float4*)(smem + BW16);
#pragma unroll
        for (int it = 0; it < 17; it++)
            d4[it * 256 + tid] = src[it * 256 + tid];
    }

    // warp decomposition
    const int wm = wid & 1;
    const int wn = wid >> 1;           // 0..3
    const int n0 = wn * 32;
    const uint32_t aOff = (uint32_t)((wm * 32 + (lane & 15)) * TSTRIDE
                                     + (lane >> 4) * 16);
    const int q = lane >> 3, r8 = lane & 7;
    const uint32_t bOff = (uint32_t)((n0 + ((q & 2) << 2) + r8) * TSTRIDE
                                     + (q & 1) * 16);
    const uint32_t aB = sbase + A16;
    const uint32_t bWB = sbase + BW16, bRB = sbase + BR16;
    const int gq = lane >> 2, t4 = lane & 3;

    float bx[4], by[4];
#pragma unroll
    for (int nf = 0; nf < 4; nf++) {
        float2 bv = *(const float2*)(bias + n0 + nf * 8 + 2 * t4);
        bx[nf] = bv.x; by[nf] = bv.y;
    }

    const int lm = tid >> 5;           // fp32 A-load base row
    const int lc4 = (tid & 31) * 4;    // fp32 A-load col
    const int hm = tid >> 4;           // fp16 A-load: rows hm + it*16
    const int hc8 = (tid & 15) * 8;    // fp16 A-load col (8 halves = 16B)

    for (int tile = blockIdx.x; tile < NT64; tile += GEMM_GRID) {
        const int row0 = tile * 64;

        __syncthreads();   // previous mainloop done reading A
        if (inSel < 0) {
            // ---- layer 0: 64x128 fp32 -> fp16 ----
#pragma unroll
            for (int it = 0; it < 8; it++) {
                int gr = row0 + lm + it * 8;
                float4 w = (gr < NN) ? *(const float4*)(Xext + gr * 128 + lc4)
                                     : make_float4(0.f, 0.f, 0.f, 0.f);
                uint32_t bo = (lm + it * 8) * TSTRIDE + lc4 * 2;
                *(uint32_t*)(smem + A16 + bo)     = packh2(w.x, w.y);
                *(uint32_t*)(smem + A16 + bo + 4) = packh2(w.z, w.w);
            }
        } else {
            // ---- layers 1-3: straight fp16 16B copies ----
#pragma unroll
            for (int it = 0; it < 4; it++) {
                int m = hm + it * 16;
                int gr = row0 + m;
                uint4 w = (gr < NN) ? *(const uint4*)(X16 + gr * 128 + hc8)
                                    : make_uint4(0u, 0u, 0u, 0u);
                *(uint4*)(smem + A16 + m * TSTRIDE + hc8 * 2) = w;
            }
        }
        __syncthreads();

        float cW[2][4][4], cR[2][4][4];
#pragma unroll
        for (int i = 0; i < 2; i++)
#pragma unroll
            for (int j = 0; j < 4; j++)
#pragma unroll
                for (int z = 0; z < 4; z++) { cW[i][j][z] = 0.f; cR[i][j][z] = 0.f; }

#pragma unroll 1
        for (int k0 = 0; k0 < 128; k0 += 16) {
            const uint32_t kB = (uint32_t)(k0 * 2);
            uint32_t a[2][4];
#pragma unroll
            for (int mf = 0; mf < 2; mf++)
                ldm4(a[mf], aB + aOff + mf * (16 * TSTRIDE) + kB);
#pragma unroll
            for (int nf2 = 0; nf2 < 2; nf2++) {
                uint32_t bb[4];
                ldm4(bb, bWB + bOff + nf2 * (16 * TSTRIDE) + kB);
#pragma unroll
                for (int mf = 0; mf < 2; mf++) {
                    mma16816h(cW[mf][nf2 * 2],     a[mf], bb[0], bb[1]);
                    mma16816h(cW[mf][nf2 * 2 + 1], a[mf], bb[2], bb[3]);
                }
                ldm4(bb, bRB + bOff + nf2 * (16 * TSTRIDE) + kB);
#pragma unroll
                for (int mf = 0; mf < 2; mf++) {
                    mma16816h(cR[mf][nf2 * 2],     a[mf], bb[0], bb[1]);
                    mma16816h(cR[mf][nf2 * 2 + 1], a[mf], bb[2], bb[3]);
                }
            }
        }

        // ---- epilogue: W -> fp16 g_h ; R + bias -> fp16 f ----
#pragma unroll
        for (int nf = 0; nf < 4; nf++) {
            const int col = n0 + nf * 8 + 2 * t4;
#pragma unroll
            for (int mf = 0; mf < 2; mf++) {
                int rlo = row0 + wm * 32 + mf * 16 + gq;
                if (rlo < NN) {
                    *(__half2*)(g_h + rlo * 128 + col) =
                        __floats2half2_rn(cW[mf][nf][0], cW[mf][nf][1]);
                    *(__half2*)(dstF + rlo * 128 + col) =
                        __floats2half2_rn(cR[mf][nf][0] + bx[nf], cR[mf][nf][1] + by[nf]);
                }
                if (rlo + 8 < NN) {
                    *(__half2*)(g_h + (rlo + 8) * 128 + col) =
                        __floats2half2_rn(cW[mf][nf][2], cW[mf][nf][3]);
                    *(__half2*)(dstF + (rlo + 8) * 128 + col) =
                        __floats2half2_rn(cR[mf][nf][2] + bx[nf], cR[mf][nf][3] + by[nf]);
                }
            }
        }
    }
}

// ---------------- graph preprocessing --------------------------------------
__global__ void k_deg(const int* __restrict__ ei) {
    int e = blockIdx.x * blockDim.x + threadIdx.x;
    if (e < NE) {
        int d = ei[NE + e];
        if (d >= 0 && d < NN) atomicAdd(&g_deg[d], 1);
    }
}

__global__ void k_off() {
    __shared__ int sh[256];
    __shared__ int base;
    const int t = threadIdx.x;
    const int i = blockIdx.x * 256 + t;
    int d = (i < NN) ? g_deg[i] : 0;
    if (i < NN) g_dinv[i] = (d > 0) ? rsqrtf((float)d) : 0.f;
    sh[t] = d;
    __syncthreads();
    for (int off = 1; off < 256; off <<= 1) {
        int v = (t >= off) ? sh[t - off] : 0;
        __syncthreads();
        sh[t] += v;
        __syncthreads();
    }
    if (t == 255) base = atomicAdd(&g_total, sh[255]);
    __syncthreads();
    if (i < NN) g_beg[i] = base + sh[t] - d;
}

// fill atomics run directly on g_beg; afterwards g_beg[i] == segment END
__global__ void k_fill(const int* __restrict__ ei) {
    int e = blockIdx.x * blockDim.x + threadIdx.x;
    if (e < NE) {
        int s = ei[e];
        int d = ei[NE + e];
        if (s < 0 || s >= NN || d < 0 || d >= NN) return;
        float w = g_dinv[s] * g_dinv[d];
        int pos = atomicAdd(&g_beg[d], 1);
        g_edge[pos] = make_uint2((uint32_t)s, __float_as_uint(w));
    }
}

// ---------------- CSR aggregation: warp per node, fp16 gather ---------------
// relu applied here; non-last: write fp16 next-layer input; last: fp32 lastOut
__global__ void k_agg(int outSel, int last, float* __restrict__ lastOut) {
    __half* f = selBuf(outSel);
    const int wid = threadIdx.x >> 5, lane = threadIdx.x & 31;
    const int i = blockIdx.x * 4 + wid;
    if (i >= NN) return;
    const int end = g_beg[i];
    const int beg = end - g_deg[i];
    const int laneOff = lane * 4;
    // init: skip connection (fp16 f from GEMM) -> fp32
    float4 acc;
    {
        uint2 u = *(const uint2*)(f + i * HH + laneOff);
        float2 a = __half22float2(*(__half2*)&u.x), b = __half22float2(*(__half2*)&u.y);
        acc = make_float4(a.x, a.y, b.x, b.y);
    }
    int e = beg;
    for (; e + 4 <= end; e += 4) {
        uint2 e0 = g_edge[e],   e1 = g_edge[e+1];
        uint2 e2 = g_edge[e+2], e3 = g_edge[e+3];
        float w0 = __uint_as_float(e0.y), w1 = __uint_as_float(e1.y);
        float w2 = __uint_as_float(e2.y), w3 = __uint_as_float(e3.y);
        uint2 u0 = *(const uint2*)(g_h + e0.x * HH + laneOff);
        uint2 u1 = *(const uint2*)(g_h + e1.x * HH + laneOff);
        uint2 u2 = *(const uint2*)(g_h + e2.x * HH + laneOff);
        uint2 u3 = *(const uint2*)(g_h + e3.x * HH + laneOff);
        float2 a0 = __half22float2(*(__half2*)&u0.x), b0 = __half22float2(*(__half2*)&u0.y);
        float2 a1 = __half22float2(*(__half2*)&u1.x), b1 = __half22float2(*(__half2*)&u1.y);
        float2 a2 = __half22float2(*(__half2*)&u2.x), b2 = __half22float2(*(__half2*)&u2.y);
        float2 a3 = __half22float2(*(__half2*)&u3.x), b3 = __half22float2(*(__half2*)&u3.y);
        acc.x += a0.x*w0 + a1.x*w1 + a2.x*w2 + a3.x*w3;
        acc.y += a0.y*w0 + a1.y*w1 + a2.y*w2 + a3.y*w3;
        acc.z += b0.x*w0 + b1.x*w1 + b2.x*w2 + b3.x*w3;
        acc.w += b0.y*w0 + b1.y*w1 + b2.y*w2 + b3.y*w3;
    }
    for (; e < end; e++) {
        uint2 ed = g_edge[e];
        float w = __uint_as_float(ed.y);
        uint2 u = *(const uint2*)(g_h + ed.x * HH + laneOff);
        float2 a = __half22float2(*(__half2*)&u.x), b = __half22float2(*(__half2*)&u.y);
        acc.x += a.x * w; acc.y += a.y * w;
        acc.z += b.x * w; acc.w += b.y * w;
    }
    acc.x = fmaxf(acc.x, 0.f); acc.y = fmaxf(acc.y, 0.f);
    acc.z = fmaxf(acc.z, 0.f); acc.w = fmaxf(acc.w, 0.f);
    if (last) {
        *(float4*)(lastOut + i * HH + laneOff) = acc;
    } else {
        uint2 o;
        *(__half2*)&o.x = __floats2half2_rn(acc.x, acc.y);
        *(__half2*)&o.y = __floats2half2_rn(acc.z, acc.w);
        *(uint2*)(f + i * HH + laneOff) = o;
    }
}

// ---------------- mean-pool accumulation (input already relu'd) -------------
__global__ void k_pool(const float* __restrict__ f,
                       const int* __restrict__ batch) {
    const int t = threadIdx.x;
    const int base = blockIdx.x * 64;
    float acc = 0.f;
    int cur = -1;
    for (int r = 0; r < 64; r++) {
        int i = base + r;
        if (i >= NN) break;
        float v = f[i * HH + t];
        int bg = batch[i];
        if (bg != cur) {
            if (cur >= 0) atomicAdd(&g_pool[cur * HH + t], acc);
            cur = bg; acc = 0.f;
        }
        acc += v;
    }
    if (cur >= 0) atomicAdd(&g_pool[cur * HH + t], acc);
    if (t == 0) {
        int c = 0; int cb = -1;
        for (int r = 0; r < 64; r++) {
            int i = base + r;
            if (i >= NN) break;
            int bg = batch[i];
            if (bg != cb) {
                if (cb >= 0) atomicAdd(&g_cnt[cb], (float)c);
                cb = bg; c = 0;
            }
            c++;
        }
        if (cb >= 0) atomicAdd(&g_cnt[cb], (float)c);
    }
}

// ---------------- MLP head + log_softmax ------------------------------------
__global__ void k_head(const float* __restrict__ l1w, const float* __restrict__ l1b,
                       const float* __restrict__ l2w, const float* __restrict__ l2b,
                       float* __restrict__ out) {
    __shared__ float p[HH];
    __shared__ float gg[HH];
    __shared__ float lg[NC];
    const int g = blockIdx.x, t = threadIdx.x;
    float c = fmaxf(g_cnt[g], 1.f);
    p[t] = g_pool[g * HH + t] / c;
    __syncthreads();
    float a = l1b[t];
#pragma unroll 8
    for (int k = 0; k < HH; k++) a += p[k] * l1w[k * HH + t];
    gg[t] = fmaxf(a, 0.f);
    __syncthreads();
    if (t < NC) {
        float a2 = l2b[t];
        for (int k = 0; k < HH; k++) a2 += gg[k] * l2w[k * NC + t];
        lg[t] = a2;
    }
    __syncthreads();
    if (t < NC) {
        float m = lg[0];
        for (int j = 1; j < NC; j++) m = fmaxf(m, lg[j]);
        float s = 0.f;
        for (int j = 0; j < NC; j++) s += expf(lg[j] - m);
        out[g * NC + t] = lg[t] - m - logf(s);
    }
}

// ---------------- launch -----------------------------------------------------
extern "C" void kernel_launch(void* const* d_in, const int* in_sizes, int n_in,
                              void* d_out, int out_size) {
    const float* x     = (const float*)d_in[0];
    const int*   ei    = (const int*)d_in[1];
    const int*   batch = (const int*)d_in[2];
    const float* W1    = (const float*)d_in[3];
    const float* R1    = (const float*)d_in[4];
    const float* b1    = (const float*)d_in[5];
    const float* Wc    = (const float*)d_in[6];
    const float* Rc    = (const float*)d_in[7];
    const float* bc    = (const float*)d_in[8];
    const float* l1w   = (const float*)d_in[9];
    const float* l1b   = (const float*)d_in[10];
    const float* l2w   = (const float*)d_in[11];
    const float* l2b   = (const float*)d_in[12];
    float* out     = (float*)d_out;
    float* lastOut = out + NG * NC;   // tuple order: (log_softmax, last)

    cudaFuncSetAttribute(k_mmagemm, cudaFuncAttributeMaxDynamicSharedMemorySize, SM2_TOTAL);

    // preprocessing: zero+weight convert fused, then CSR build
    k_pre <<<204, 256>>>(W1, R1, Wc, Rc);
    k_deg <<<(NE + 255) / 256, 256>>>(ei);
    k_off <<<(NN + 255) / 256, 256>>>();
    k_fill<<<(NE + 255) / 256, 256>>>(ei);

    // 4 GCS layers; relu lives in k_agg; last agg writes fp32 lastOut
    int inSel = -1;
    int outSel = 0;
    for (int l = 0; l < 4; l++) {
        const float* b = (l == 0) ? b1 : bc + (l - 1) * HH;
        k_mmagemm<<<GEMM_GRID, 256, SM2_TOTAL>>>(x, inSel, outSel, l, b);
        k_agg<<<(NN + 3) / 4, 128>>>(outSel, (l == 3) ? 1 : 0, lastOut);
        inSel = outSel;
        outSel ^= 1;
    }

    k_pool<<<(NN + 63) / 64, 128>>>(lastOut, batch);
    k_head<<<NG, 128>>>(l1w, l1b, l2w, l2b, out);
}